// round 12
// baseline (speedup 1.0000x reference)
#include <cuda_runtime.h>
#include <cuda_fp16.h>
#include <math.h>
#include <cstdint>

#define NN 50000
#define EE 800000
#define HH 128
#define GG 128
#define CC 10
#define SCAN_BLK 49   // ceil(50000/1024)

// ---------------- static device scratch ----------------
__device__ int      g_deg[NN];
__device__ int      g_starts[NN + 1];
__device__ unsigned g_sync[SCAN_BLK];      // lookback scan: READY bit | inclusive prefix
__device__ int      g_cursor[NN];
__device__ int      g_src[EE];
__device__ float    g_dinv[NN];
__device__ __half   g_xh[(size_t)NN * HH];   // fp16 x
__device__ __half   g_h1[(size_t)NN * HH];   // fp16 h1
__device__ __half   g_hq[(size_t)NN * HH];   // fp16 hq2 (conv2 GEMM out)
__device__ __half   g_h2[(size_t)NN * HH];   // fp16 hq3 (conv3 GEMM out)
__device__ __half   g_WcH[4 * HH * HH];      // fp16 weights hi
__device__ __half   g_WcL[4 * HH * HH];      // fp16 weights lo (residual)
__device__ float    g_pool[GG * HH];

// ---------------- fused zero + conversions ----------------
__global__ void k_zero_conv(const float4* __restrict__ x4,
                            const float* __restrict__ W0, const float* __restrict__ W1,
                            const float* __restrict__ W2, const float* __restrict__ W3) {
    int p = blockIdx.x * blockDim.x + threadIdx.x;
    if (p < NN) g_deg[p] = 0;
    if (p < GG * HH) g_pool[p] = 0.f;
    if (p < SCAN_BLK) g_sync[p] = 0u;
    if (p < NN * HH / 4) {
        float4 v = __ldg(&x4[p]);
        __half2 a = __floats2half2_rn(v.x, v.y);
        __half2 b = __floats2half2_rn(v.z, v.w);
        uint2 o; o.x = *(uint32_t*)&a; o.y = *(uint32_t*)&b;
        *(uint2*)&g_xh[(size_t)p * 4] = o;
    }
    if (p < HH * HH) {
        const float* Ws[4] = {W0, W1, W2, W3};
        #pragma unroll
        for (int w = 0; w < 4; w++) {
            float v = __ldg(&Ws[w][p]);
            __half h = __float2half(v);
            g_WcH[w * HH * HH + p] = h;
            g_WcL[w * HH * HH + p] = __float2half(v - __half2float(h));
        }
    }
}

__global__ void k_deg(const int* __restrict__ col) {
    int e = blockIdx.x * blockDim.x + threadIdx.x;
    if (e < EE) atomicAdd(&g_deg[col[e]], 1);
}

// ---- single-kernel exclusive scan (decoupled lookback over 49 resident blocks)
//      + dinv + cursor init ----
__global__ void k_scan1() {
    __shared__ int warp_sums[32];
    __shared__ int s_carry;
    int tid = threadIdx.x, bid = blockIdx.x;
    int lane = tid & 31, wid = tid >> 5;
    int i = bid * 1024 + tid;
    int v = (i < NN) ? g_deg[i] : 0;
    int s = v;
    #pragma unroll
    for (int o = 1; o < 32; o <<= 1) {
        int t = __shfl_up_sync(0xFFFFFFFFu, s, o);
        if (lane >= o) s += t;
    }
    if (lane == 31) warp_sums[wid] = s;
    __syncthreads();
    if (wid == 0) {
        int ws = warp_sums[lane];
        #pragma unroll
        for (int o = 1; o < 32; o <<= 1) {
            int t = __shfl_up_sync(0xFFFFFFFFu, ws, o);
            if (lane >= o) ws += t;
        }
        warp_sums[lane] = ws;
    }
    __syncthreads();
    int offset = (wid > 0) ? warp_sums[wid - 1] : 0;
    int ex = offset + s - v;       // in-block exclusive
    if (tid == 1023) {
        int T = offset + s;        // block total
        unsigned prefix = 0u;
        if (bid > 0) {
            unsigned w;
            do { w = atomicAdd(&g_sync[bid - 1], 0u); } while (!(w & 0x80000000u));
            prefix = w & 0x7FFFFFFFu;
        }
        atomicExch(&g_sync[bid], 0x80000000u | (prefix + (unsigned)T));
        s_carry = (int)prefix;
        if (bid == SCAN_BLK - 1) g_starts[NN] = (int)prefix + T;
    }
    __syncthreads();
    int carry = s_carry;
    if (i < NN) {
        int st = carry + ex;
        g_starts[i] = st;
        g_cursor[i] = st;
        g_dinv[i] = rsqrtf((float)(g_deg[i] + 1));
    }
}

__global__ void k_fill(const int* __restrict__ row, const int* __restrict__ col) {
    int e = blockIdx.x * blockDim.x + threadIdx.x;
    if (e < EE) {
        int c = col[e];
        int p = atomicAdd(&g_cursor[c], 1);
        g_src[p] = row[e];
    }
}

// ---------------- helpers ----------------
__device__ __forceinline__ void acc_half4(float4& acc, uint32_t lo, uint32_t hi) {
    float2 fa = __half22float2(*(__half2*)&lo);
    float2 fb = __half22float2(*(__half2*)&hi);
    acc.x += fa.x; acc.y += fa.y; acc.z += fb.x; acc.w += fb.y;
}

// ---------------- HMMA GEMM (fp16 A, split-fp16 W, ldmatrix, fused agg prologue) ----------------
#define FL_RELU 2
#define FL_DINV 4
#define FL_AGGP 8    // prologue: A = gather-sum of src rows (no self, no norm)
#define FL_AGGN 16   // prologue: A = relu(dinv*(self+sum) + aggbias)
#define APITCH 136
#define GEMM_SMEM (3 * 128 * APITCH * 2)

__device__ __forceinline__ uint32_t smem_u32(const void* p) {
    uint32_t a;
    asm("{ .reg .u64 t; cvta.to.shared.u64 t, %1; cvt.u32.u64 %0, t; }" : "=r"(a) : "l"(p));
    return a;
}
__device__ __forceinline__ void ldsm_x4(uint32_t& r0, uint32_t& r1, uint32_t& r2, uint32_t& r3,
                                        uint32_t addr) {
    asm volatile("ldmatrix.sync.aligned.m8n8.x4.shared.b16 {%0,%1,%2,%3}, [%4];"
        : "=r"(r0), "=r"(r1), "=r"(r2), "=r"(r3) : "r"(addr));
}
__device__ __forceinline__ void mma16816(float* c, const uint32_t* a, uint32_t b0, uint32_t b1) {
    asm volatile("mma.sync.aligned.m16n8k16.row.col.f32.f16.f16.f32 "
        "{%0,%1,%2,%3}, {%4,%5,%6,%7}, {%8,%9}, {%0,%1,%2,%3};"
        : "+f"(c[0]), "+f"(c[1]), "+f"(c[2]), "+f"(c[3])
        : "r"(a[0]), "r"(a[1]), "r"(a[2]), "r"(a[3]), "r"(b0), "r"(b1));
}

__device__ __forceinline__ void load_tile16(__half* dst, const __half* src, int m0,
                                            int bound, int tid) {
    const uint4* s4 = (const uint4*)src;
    #pragma unroll 2
    for (int p = tid; p < 2048; p += 256) {
        int row = p >> 4, c8 = p & 15;
        int m = m0 + row;
        uint4 v = make_uint4(0u, 0u, 0u, 0u);
        if (m < bound) v = __ldg(&s4[(size_t)m * 16 + c8]);
        *(uint4*)&dst[row * APITCH + c8 * 8] = v;
    }
}

struct Frag { float c[2][8][4]; };

__device__ __forceinline__ void mma_stage2(Frag& f, uint32_t aBase, uint32_t whBase,
                                           uint32_t wlBase, int wm, int wn, int lane) {
    int lr = lane & 7, q = lane >> 3;
    int arow = wm + ((q & 1) << 3) + lr;
    int acol = (q >> 1) << 3;
    int brow = wn + ((q >> 1) << 3) + lr;
    int bcol = (q & 1) << 3;
    #pragma unroll
    for (int ks = 0; ks < 8; ks++) {
        int kb0 = ks * 16;
        uint32_t a[2][4];
        #pragma unroll
        for (int mt = 0; mt < 2; mt++) {
            uint32_t addr = aBase + (uint32_t)(((arow + mt * 16) * APITCH + kb0 + acol) * 2);
            ldsm_x4(a[mt][0], a[mt][1], a[mt][2], a[mt][3], addr);
        }
        #pragma unroll
        for (int pass = 0; pass < 2; pass++) {
            uint32_t wBase = pass ? wlBase : whBase;
            #pragma unroll
            for (int ntp = 0; ntp < 4; ntp++) {
                uint32_t addr = wBase + (uint32_t)(((brow + ntp * 16) * APITCH + kb0 + bcol) * 2);
                uint32_t b0e, b1e, b0o, b1o;
                ldsm_x4(b0e, b1e, b0o, b1o, addr);
                mma16816(f.c[0][2 * ntp],     a[0], b0e, b1e);
                mma16816(f.c[1][2 * ntp],     a[1], b0e, b1e);
                mma16816(f.c[0][2 * ntp + 1], a[0], b0o, b1o);
                mma16816(f.c[1][2 * ntp + 1], a[1], b0o, b1o);
            }
        }
    }
}

// C[M,128] = Aeff@W[w0]^T (+ A2@W[w1]^T) (+bias) (*dinv) (relu) -> fp16 out
// Aeff: raw A rows, or gathered per FL_AGGP / FL_AGGN (aggbias used by AGGN).
__global__ __launch_bounds__(256, 2) void k_gemm(
    const __half* __restrict__ A, int w0,
    const __half* __restrict__ A2, int w1,
    const float* __restrict__ bias, const float* __restrict__ aggbias,
    int flags, __half* __restrict__ outp)
{
    extern __shared__ __half sm[];
    __half* Ah = sm;
    __half* Wh = Ah + 128 * APITCH;
    __half* Wl = Wh + 128 * APITCH;
    int tid = threadIdx.x, wid = tid >> 5, lane = tid & 31;
    int m0 = blockIdx.x * 128;
    int wm = (wid & 3) * 32;
    int wn = (wid >> 2) * 64;
    int g = lane >> 2, tig = lane & 3;
    uint32_t aBase = smem_u32(Ah), whBase = smem_u32(Wh), wlBase = smem_u32(Wl);

    Frag f;
    #pragma unroll
    for (int mt = 0; mt < 2; mt++)
        #pragma unroll
        for (int nt = 0; nt < 8; nt++)
            #pragma unroll
            for (int j = 0; j < 4; j++) f.c[mt][nt][j] = 0.f;

    // ---- A tile: gather-aggregate or direct load ----
    if (flags & (FL_AGGP | FL_AGGN)) {
        const uint4* srcv = (const uint4*)A;
        int hw = tid >> 4, sub = tid & 15;
        #pragma unroll 1
        for (int r8 = 0; r8 < 8; r8++) {
            int rowi = hw * 8 + r8;
            int node = m0 + rowi;
            float4 acc0 = make_float4(0.f, 0.f, 0.f, 0.f);
            float4 acc1 = make_float4(0.f, 0.f, 0.f, 0.f);
            if (node < NN) {
                if (flags & FL_AGGN) {
                    uint4 v = __ldg(&srcv[(size_t)node * 16 + sub]);  // self
                    acc_half4(acc0, v.x, v.y);
                    acc_half4(acc1, v.z, v.w);
                }
                int s = g_starts[node], e = g_starts[node + 1];
                #pragma unroll 4
                for (int j = s; j < e; j++) {
                    int u = __ldg(&g_src[j]);
                    uint4 v = __ldg(&srcv[(size_t)u * 16 + sub]);
                    acc_half4(acc0, v.x, v.y);
                    acc_half4(acc1, v.z, v.w);
                }
                if (flags & FL_AGGN) {
                    float dv = g_dinv[node];
                    float4 b0 = __ldg(&((const float4*)aggbias)[sub * 2]);
                    float4 b1 = __ldg(&((const float4*)aggbias)[sub * 2 + 1]);
                    acc0.x = fmaxf(fmaf(acc0.x, dv, b0.x), 0.f);
                    acc0.y = fmaxf(fmaf(acc0.y, dv, b0.y), 0.f);
                    acc0.z = fmaxf(fmaf(acc0.z, dv, b0.z), 0.f);
                    acc0.w = fmaxf(fmaf(acc0.w, dv, b0.w), 0.f);
                    acc1.x = fmaxf(fmaf(acc1.x, dv, b1.x), 0.f);
                    acc1.y = fmaxf(fmaf(acc1.y, dv, b1.y), 0.f);
                    acc1.z = fmaxf(fmaf(acc1.z, dv, b1.z), 0.f);
                    acc1.w = fmaxf(fmaf(acc1.w, dv, b1.w), 0.f);
                }
            }
            __half2 h0 = __floats2half2_rn(acc0.x, acc0.y);
            __half2 h1 = __floats2half2_rn(acc0.z, acc0.w);
            __half2 h2 = __floats2half2_rn(acc1.x, acc1.y);
            __half2 h3 = __floats2half2_rn(acc1.z, acc1.w);
            uint4 o;
            o.x = *(uint32_t*)&h0; o.y = *(uint32_t*)&h1;
            o.z = *(uint32_t*)&h2; o.w = *(uint32_t*)&h3;
            *(uint4*)&Ah[rowi * APITCH + sub * 8] = o;
        }
    } else {
        load_tile16(Ah, A, m0, NN, tid);
    }
    load_tile16(Wh, g_WcH + (size_t)w0 * HH * HH, 0, HH, tid);
    load_tile16(Wl, g_WcL + (size_t)w0 * HH * HH, 0, HH, tid);
    __syncthreads();
    mma_stage2(f, aBase, whBase, wlBase, wm, wn, lane);

    if (A2) {
        __syncthreads();
        load_tile16(Ah, A2, m0, NN, tid);
        load_tile16(Wh, g_WcH + (size_t)w1 * HH * HH, 0, HH, tid);
        load_tile16(Wl, g_WcL + (size_t)w1 * HH * HH, 0, HH, tid);
        __syncthreads();
        mma_stage2(f, aBase, whBase, wlBase, wm, wn, lane);
    }

    #pragma unroll
    for (int mt = 0; mt < 2; mt++) {
        #pragma unroll
        for (int half = 0; half < 2; half++) {
            int m = m0 + wm + mt * 16 + g + half * 8;
            if (m >= NN) continue;
            float dv = (flags & FL_DINV) ? g_dinv[m] : 1.f;
            #pragma unroll
            for (int nt = 0; nt < 8; nt++) {
                int col = wn + nt * 8 + 2 * tig;
                float vx = f.c[mt][nt][half * 2 + 0];
                float vy = f.c[mt][nt][half * 2 + 1];
                if (bias) {
                    float2 b2 = __ldg((const float2*)&bias[col]);
                    vx += b2.x; vy += b2.y;
                }
                if (flags & FL_DINV) { vx *= dv; vy *= dv; }
                if (flags & FL_RELU) { vx = fmaxf(vx, 0.f); vy = fmaxf(vy, 0.f); }
                __half2 hv = __floats2half2_rn(vx, vy);
                *(__half2*)&outp[(size_t)m * HH + col] = hv;
            }
        }
    }
}

// ---------------- fused conv3-agg + mean-pool ----------------
// h3[n] = dinv[n]*(hq3[n] + sum_src hq3[src]) + b3 ; run-length sum into g_pool
__global__ void k_pool3(const int* __restrict__ batch, const float* __restrict__ b3) {
    int c = threadIdx.x;  // feature
    int n0 = blockIdx.x * 64;
    int n1 = n0 + 64; if (n1 > NN) n1 = NN;
    if (n0 >= NN) return;
    const __half* hq3 = g_h2;
    float bc = __ldg(&b3[c]);
    float racc = 0.f;
    int cur = __ldg(&batch[n0]);
    for (int n = n0; n < n1; n++) {
        int b = __ldg(&batch[n]);
        if (b != cur) { atomicAdd(&g_pool[cur * HH + c], racc); racc = 0.f; cur = b; }
        float acc = __half2float(__ldg(&hq3[(size_t)n * HH + c]));  // self
        int s = g_starts[n], e = g_starts[n + 1];
        #pragma unroll 8
        for (int j = s; j < e; j++) {
            int u = __ldg(&g_src[j]);
            acc += __half2float(__ldg(&hq3[(size_t)u * HH + c]));
        }
        racc += fmaf(acc, g_dinv[n], bc);
    }
    atomicAdd(&g_pool[cur * HH + c], racc);
}

// lower_bound on sorted batch: first i with batch[i] >= val
__device__ __forceinline__ int lb_batch(const int* __restrict__ batch, int val) {
    int lo = 0, hi = NN;
    while (lo < hi) {
        int mid = (lo + hi) >> 1;
        if (__ldg(&batch[mid]) < val) lo = mid + 1; else hi = mid;
    }
    return lo;
}

__global__ void k_final(const int* __restrict__ batch,
                        const float* __restrict__ Wl, const float* __restrict__ bl,
                        float* __restrict__ dout) {
    __shared__ float ws[4];
    __shared__ float xs[HH];
    __shared__ float winv[CC];
    int g = blockIdx.x, t = threadIdx.x;
    int cnt = lb_batch(batch, g + 1) - lb_batch(batch, g);
    float c = fmaxf((float)cnt, 1.f);
    float v = g_pool[g * HH + t] / c;
    float s = v * v;
    #pragma unroll
    for (int o = 16; o > 0; o >>= 1) s += __shfl_down_sync(0xFFFFFFFFu, s, o);
    if ((t & 31) == 0) ws[t >> 5] = s;
    if (t < CC) {
        float sw = 0.f;
        #pragma unroll 8
        for (int k = 0; k < HH; k++) { float w = __ldg(&Wl[t * HH + k]); sw = fmaf(w, w, sw); }
        winv[t] = 1.f / fmaxf(sqrtf(sw), 1e-12f);
    }
    __syncthreads();
    float tot = ws[0] + ws[1] + ws[2] + ws[3];
    float nrm = fmaxf(sqrtf(tot), 1e-12f);
    float xn = v / nrm;
    dout[g * HH + t] = xn;
    xs[t] = xn;
    __syncthreads();
    if (t < CC) {
        float s2 = 0.f;
        #pragma unroll 8
        for (int k = 0; k < HH; k++) s2 = fmaf(xs[k], __ldg(&Wl[t * HH + k]), s2);
        dout[GG * HH + g * CC + t] = fmaf(s2, winv[t], bl[t]);
    }
}

// ---------------- launch ----------------
extern "C" void kernel_launch(void* const* d_in, const int* in_sizes, int n_in,
                              void* d_out, int out_size) {
    const float* x    = (const float*)d_in[0];
    const int*   ei   = (const int*)d_in[1];
    const int*   batch= (const int*)d_in[2];
    const float* W1r  = (const float*)d_in[3];
    const float* b1   = (const float*)d_in[4];
    const float* W1x  = (const float*)d_in[5];
    const float* W2   = (const float*)d_in[6];
    const float* b2   = (const float*)d_in[7];
    const float* W3   = (const float*)d_in[8];
    const float* b3   = (const float*)d_in[9];
    const float* Wl   = (const float*)d_in[10];
    const float* bl   = (const float*)d_in[11];
    const int* row = ei;
    const int* col = ei + EE;
    float* out = (float*)d_out;

    cudaFuncSetAttribute(k_gemm, cudaFuncAttributeMaxDynamicSharedMemorySize, GEMM_SMEM);

    __half *xh, *h1, *hq, *h2;
    cudaGetSymbolAddress((void**)&xh, g_xh);
    cudaGetSymbolAddress((void**)&h1, g_h1);
    cudaGetSymbolAddress((void**)&hq, g_hq);
    cudaGetSymbolAddress((void**)&h2, g_h2);

    // preprocessing (4 launches)
    k_zero_conv<<<(NN * HH / 4 + 255) / 256, 256>>>((const float4*)x, W1r, W1x, W2, W3);
    k_deg<<<(EE + 255) / 256, 256>>>(col);
    k_scan1<<<SCAN_BLK, 1024>>>();
    k_fill<<<(EE + 255) / 256, 256>>>(row, col);

    int GB = (NN + 127) / 128;

    // conv1: h1 = relu(gather(x)@W0^T + x@W1^T + b1)    [agg fused in prologue]
    k_gemm<<<GB, 256, GEMM_SMEM>>>(xh, 0, xh, 1, b1, nullptr, FL_RELU | FL_AGGP, h1);

    // conv2 matmul: hq2 = (h1@W2^T)*dinv
    k_gemm<<<GB, 256, GEMM_SMEM>>>(h1, 2, nullptr, 0, nullptr, nullptr, FL_DINV, hq);

    // conv2 agg + conv3 matmul: hq3 = (relu(dinv*(hq2 self+sum)+b2) @ W3^T)*dinv
    k_gemm<<<GB, 256, GEMM_SMEM>>>(hq, 3, nullptr, 0, nullptr, b2, FL_DINV | FL_AGGN, h2);

    // conv3 agg + bias + mean-pool (fused), then normalize + classifier
    k_pool3<<<(NN + 63) / 64, 128>>>(batch, b3);
    k_final<<<GG, HH>>>(batch, Wl, bl, out);
}

// round 13
// speedup vs baseline: 1.6824x; 1.6824x over previous
#include <cuda_runtime.h>
#include <cuda_fp16.h>
#include <math.h>
#include <cstdint>

#define NN 50000
#define EE 800000
#define HH 128
#define GG 128
#define CC 10
#define SCAN_BLK 49   // ceil(50000/1024)

// ---------------- static device scratch ----------------
__device__ int      g_deg[NN];
__device__ int      g_starts[NN + 1];
__device__ unsigned g_sync[SCAN_BLK];      // lookback scan: READY bit | inclusive prefix
__device__ int      g_cursor[NN];
__device__ int      g_src[EE];
__device__ float    g_dinv[NN];
__device__ __half   g_xh[(size_t)NN * HH];   // fp16 x
__device__ __half   g_agg[(size_t)NN * HH];  // fp16 aggregated x
__device__ __half   g_h1[(size_t)NN * HH];   // fp16 h1
__device__ __half   g_h2[(size_t)NN * HH];   // fp16 h2
__device__ __half   g_hq[(size_t)NN * HH];   // fp16 hq (conv2/3 GEMM out)
__device__ __half   g_h3[(size_t)NN * HH];   // fp16 h3 for pooling
__device__ __half   g_WcH[4 * HH * HH];      // fp16 weights hi
__device__ __half   g_WcL[4 * HH * HH];      // fp16 weights lo (residual)
__device__ float    g_pool[GG * HH];

// ---------------- fused zero + conversions ----------------
__global__ void k_zero_conv(const float4* __restrict__ x4,
                            const float* __restrict__ W0, const float* __restrict__ W1,
                            const float* __restrict__ W2, const float* __restrict__ W3) {
    int p = blockIdx.x * blockDim.x + threadIdx.x;
    if (p < NN) g_deg[p] = 0;
    if (p < GG * HH) g_pool[p] = 0.f;
    if (p < SCAN_BLK) g_sync[p] = 0u;
    if (p < NN * HH / 4) {
        float4 v = __ldg(&x4[p]);
        __half2 a = __floats2half2_rn(v.x, v.y);
        __half2 b = __floats2half2_rn(v.z, v.w);
        uint2 o; o.x = *(uint32_t*)&a; o.y = *(uint32_t*)&b;
        *(uint2*)&g_xh[(size_t)p * 4] = o;
    }
    if (p < HH * HH) {
        const float* Ws[4] = {W0, W1, W2, W3};
        #pragma unroll
        for (int w = 0; w < 4; w++) {
            float v = __ldg(&Ws[w][p]);
            __half h = __float2half(v);
            g_WcH[w * HH * HH + p] = h;
            g_WcL[w * HH * HH + p] = __float2half(v - __half2float(h));
        }
    }
}

__global__ void k_deg(const int* __restrict__ col) {
    int e = blockIdx.x * blockDim.x + threadIdx.x;
    if (e < EE) atomicAdd(&g_deg[col[e]], 1);
}

// ---- single-kernel exclusive scan (decoupled lookback, 49 resident blocks)
//      + dinv + cursor init ----
__global__ void k_scan1() {
    __shared__ int warp_sums[32];
    __shared__ int s_carry;
    int tid = threadIdx.x, bid = blockIdx.x;
    int lane = tid & 31, wid = tid >> 5;
    int i = bid * 1024 + tid;
    int v = (i < NN) ? g_deg[i] : 0;
    int s = v;
    #pragma unroll
    for (int o = 1; o < 32; o <<= 1) {
        int t = __shfl_up_sync(0xFFFFFFFFu, s, o);
        if (lane >= o) s += t;
    }
    if (lane == 31) warp_sums[wid] = s;
    __syncthreads();
    if (wid == 0) {
        int ws = warp_sums[lane];
        #pragma unroll
        for (int o = 1; o < 32; o <<= 1) {
            int t = __shfl_up_sync(0xFFFFFFFFu, ws, o);
            if (lane >= o) ws += t;
        }
        warp_sums[lane] = ws;
    }
    __syncthreads();
    int offset = (wid > 0) ? warp_sums[wid - 1] : 0;
    int ex = offset + s - v;       // in-block exclusive
    if (tid == 1023) {
        int T = offset + s;        // block total
        unsigned prefix = 0u;
        if (bid > 0) {
            unsigned w;
            do { w = atomicAdd(&g_sync[bid - 1], 0u); } while (!(w & 0x80000000u));
            prefix = w & 0x7FFFFFFFu;
        }
        atomicExch(&g_sync[bid], 0x80000000u | (prefix + (unsigned)T));
        s_carry = (int)prefix;
        if (bid == SCAN_BLK - 1) g_starts[NN] = (int)prefix + T;
    }
    __syncthreads();
    int carry = s_carry;
    if (i < NN) {
        int st = carry + ex;
        g_starts[i] = st;
        g_cursor[i] = st;
        g_dinv[i] = rsqrtf((float)(g_deg[i] + 1));
    }
}

__global__ void k_fill(const int* __restrict__ row, const int* __restrict__ col) {
    int e = blockIdx.x * blockDim.x + threadIdx.x;
    if (e < EE) {
        int c = col[e];
        int p = atomicAdd(&g_cursor[c], 1);
        g_src[p] = row[e];
    }
}

// ---------------- aggregation (half-warp per node, uint4 lanes) ----------------
__device__ __forceinline__ void acc_half4(float4& acc, uint32_t lo, uint32_t hi) {
    float2 fa = __half22float2(*(__half2*)&lo);
    float2 fb = __half22float2(*(__half2*)&hi);
    acc.x += fa.x; acc.y += fa.y; acc.z += fb.x; acc.w += fb.y;
}
__device__ __forceinline__ void store_half8(__half* dst, size_t idx, float4 a, float4 b) {
    __half2 h0 = __floats2half2_rn(a.x, a.y);
    __half2 h1 = __floats2half2_rn(a.z, a.w);
    __half2 h2 = __floats2half2_rn(b.x, b.y);
    __half2 h3 = __floats2half2_rn(b.z, b.w);
    uint4 o;
    o.x = *(uint32_t*)&h0; o.y = *(uint32_t*)&h1;
    o.z = *(uint32_t*)&h2; o.w = *(uint32_t*)&h3;
    *(uint4*)&dst[idx] = o;
}

// gather x (fp16) -> g_agg; 2 nodes/warp, 16 lanes x 16B per row
__global__ void k_agg1() {
    int node = blockIdx.x * 16 + (threadIdx.x >> 4);
    if (node >= NN) return;
    int sub = threadIdx.x & 15;
    const uint4* xh = (const uint4*)g_xh;
    float4 acc0 = make_float4(0.f, 0.f, 0.f, 0.f);
    float4 acc1 = make_float4(0.f, 0.f, 0.f, 0.f);
    int s = g_starts[node], e = g_starts[node + 1];
    #pragma unroll 4
    for (int j = s; j < e; j++) {
        int u = __ldg(&g_src[j]);
        uint4 v = __ldg(&xh[(size_t)u * 16 + sub]);
        acc_half4(acc0, v.x, v.y);
        acc_half4(acc1, v.z, v.w);
    }
    store_half8(g_agg, (size_t)node * HH + sub * 8, acc0, acc1);
}

// gather g_hq (fp16), self+neigh, *dinv, +bias, optional relu; fp16 out
__global__ void k_aggn(const float* __restrict__ bias, int relu, int mode) {
    int node = blockIdx.x * 16 + (threadIdx.x >> 4);
    if (node >= NN) return;
    int sub = threadIdx.x & 15;
    const uint4* hq = (const uint4*)g_hq;
    float4 acc0 = make_float4(0.f, 0.f, 0.f, 0.f);
    float4 acc1 = make_float4(0.f, 0.f, 0.f, 0.f);
    {
        uint4 v = __ldg(&hq[(size_t)node * 16 + sub]);  // self
        acc_half4(acc0, v.x, v.y);
        acc_half4(acc1, v.z, v.w);
    }
    int s = g_starts[node], e = g_starts[node + 1];
    #pragma unroll 4
    for (int j = s; j < e; j++) {
        int u = __ldg(&g_src[j]);
        uint4 v = __ldg(&hq[(size_t)u * 16 + sub]);
        acc_half4(acc0, v.x, v.y);
        acc_half4(acc1, v.z, v.w);
    }
    float dv = g_dinv[node];
    float4 b0 = __ldg(&((const float4*)bias)[sub * 2]);
    float4 b1 = __ldg(&((const float4*)bias)[sub * 2 + 1]);
    float4 r0, r1;
    r0.x = fmaf(acc0.x, dv, b0.x); r0.y = fmaf(acc0.y, dv, b0.y);
    r0.z = fmaf(acc0.z, dv, b0.z); r0.w = fmaf(acc0.w, dv, b0.w);
    r1.x = fmaf(acc1.x, dv, b1.x); r1.y = fmaf(acc1.y, dv, b1.y);
    r1.z = fmaf(acc1.z, dv, b1.z); r1.w = fmaf(acc1.w, dv, b1.w);
    if (relu) {
        r0.x = fmaxf(r0.x, 0.f); r0.y = fmaxf(r0.y, 0.f);
        r0.z = fmaxf(r0.z, 0.f); r0.w = fmaxf(r0.w, 0.f);
        r1.x = fmaxf(r1.x, 0.f); r1.y = fmaxf(r1.y, 0.f);
        r1.z = fmaxf(r1.z, 0.f); r1.w = fmaxf(r1.w, 0.f);
    }
    if (mode) {
        store_half8(g_h2, (size_t)node * HH + sub * 8, r0, r1);
    } else {
        store_half8(g_h3, (size_t)node * HH + sub * 8, r0, r1);
    }
}

// ---------------- HMMA GEMM (fp16 A, split-fp16 W, ldmatrix) ----------------
#define FL_RELU 2
#define FL_DINV 4
#define APITCH 136
#define GEMM_SMEM (3 * 128 * APITCH * 2)

__device__ __forceinline__ uint32_t smem_u32(const void* p) {
    uint32_t a;
    asm("{ .reg .u64 t; cvta.to.shared.u64 t, %1; cvt.u32.u64 %0, t; }" : "=r"(a) : "l"(p));
    return a;
}
__device__ __forceinline__ void ldsm_x4(uint32_t& r0, uint32_t& r1, uint32_t& r2, uint32_t& r3,
                                        uint32_t addr) {
    asm volatile("ldmatrix.sync.aligned.m8n8.x4.shared.b16 {%0,%1,%2,%3}, [%4];"
        : "=r"(r0), "=r"(r1), "=r"(r2), "=r"(r3) : "r"(addr));
}
__device__ __forceinline__ void mma16816(float* c, const uint32_t* a, uint32_t b0, uint32_t b1) {
    asm volatile("mma.sync.aligned.m16n8k16.row.col.f32.f16.f16.f32 "
        "{%0,%1,%2,%3}, {%4,%5,%6,%7}, {%8,%9}, {%0,%1,%2,%3};"
        : "+f"(c[0]), "+f"(c[1]), "+f"(c[2]), "+f"(c[3])
        : "r"(a[0]), "r"(a[1]), "r"(a[2]), "r"(a[3]), "r"(b0), "r"(b1));
}

// copy fp16 tile [128 x 128] global -> padded smem (16B vectors)
__device__ __forceinline__ void load_tile16(__half* dst, const __half* src, int m0,
                                            int bound, int tid) {
    const uint4* s4 = (const uint4*)src;
    #pragma unroll 2
    for (int p = tid; p < 2048; p += 256) {
        int row = p >> 4, c8 = p & 15;
        int m = m0 + row;
        uint4 v = make_uint4(0u, 0u, 0u, 0u);
        if (m < bound) v = __ldg(&s4[(size_t)m * 16 + c8]);
        *(uint4*)&dst[row * APITCH + c8 * 8] = v;
    }
}

struct Frag { float c[2][8][4]; };

// one stage-pair: f += A*Wh^T + A*Wl^T
__device__ __forceinline__ void mma_stage2(Frag& f, uint32_t aBase, uint32_t whBase,
                                           uint32_t wlBase, int wm, int wn, int lane) {
    int lr = lane & 7, q = lane >> 3;
    int arow = wm + ((q & 1) << 3) + lr;
    int acol = (q >> 1) << 3;
    int brow = wn + ((q >> 1) << 3) + lr;
    int bcol = (q & 1) << 3;
    #pragma unroll
    for (int ks = 0; ks < 8; ks++) {
        int kb0 = ks * 16;
        uint32_t a[2][4];
        #pragma unroll
        for (int mt = 0; mt < 2; mt++) {
            uint32_t addr = aBase + (uint32_t)(((arow + mt * 16) * APITCH + kb0 + acol) * 2);
            ldsm_x4(a[mt][0], a[mt][1], a[mt][2], a[mt][3], addr);
        }
        #pragma unroll
        for (int pass = 0; pass < 2; pass++) {
            uint32_t wBase = pass ? wlBase : whBase;
            #pragma unroll
            for (int ntp = 0; ntp < 4; ntp++) {
                uint32_t addr = wBase + (uint32_t)(((brow + ntp * 16) * APITCH + kb0 + bcol) * 2);
                uint32_t b0e, b1e, b0o, b1o;
                ldsm_x4(b0e, b1e, b0o, b1o, addr);
                mma16816(f.c[0][2 * ntp],     a[0], b0e, b1e);
                mma16816(f.c[1][2 * ntp],     a[1], b0e, b1e);
                mma16816(f.c[0][2 * ntp + 1], a[0], b0o, b1o);
                mma16816(f.c[1][2 * ntp + 1], a[1], b0o, b1o);
            }
        }
    }
}

// C[M,128] = A@W[w0]^T (+ A2@W[w1]^T) (+bias) (*dinv) (relu) -> fp16 out
__global__ __launch_bounds__(256, 2) void k_gemm(
    const __half* __restrict__ A, int w0,
    const __half* __restrict__ A2, int w1,
    const float* __restrict__ bias, int flags,
    __half* __restrict__ outp)
{
    extern __shared__ __half sm[];
    __half* Ah = sm;
    __half* Wh = Ah + 128 * APITCH;
    __half* Wl = Wh + 128 * APITCH;
    int tid = threadIdx.x, wid = tid >> 5, lane = tid & 31;
    int m0 = blockIdx.x * 128;
    int wm = (wid & 3) * 32;
    int wn = (wid >> 2) * 64;
    int g = lane >> 2, tig = lane & 3;
    uint32_t aBase = smem_u32(Ah), whBase = smem_u32(Wh), wlBase = smem_u32(Wl);

    Frag f;
    #pragma unroll
    for (int mt = 0; mt < 2; mt++)
        #pragma unroll
        for (int nt = 0; nt < 8; nt++)
            #pragma unroll
            for (int j = 0; j < 4; j++) f.c[mt][nt][j] = 0.f;

    load_tile16(Ah, A, m0, NN, tid);
    load_tile16(Wh, g_WcH + (size_t)w0 * HH * HH, 0, HH, tid);
    load_tile16(Wl, g_WcL + (size_t)w0 * HH * HH, 0, HH, tid);
    __syncthreads();
    mma_stage2(f, aBase, whBase, wlBase, wm, wn, lane);

    if (A2) {
        __syncthreads();
        load_tile16(Ah, A2, m0, NN, tid);
        load_tile16(Wh, g_WcH + (size_t)w1 * HH * HH, 0, HH, tid);
        load_tile16(Wl, g_WcL + (size_t)w1 * HH * HH, 0, HH, tid);
        __syncthreads();
        mma_stage2(f, aBase, whBase, wlBase, wm, wn, lane);
    }

    #pragma unroll
    for (int mt = 0; mt < 2; mt++) {
        #pragma unroll
        for (int half = 0; half < 2; half++) {
            int m = m0 + wm + mt * 16 + g + half * 8;
            if (m >= NN) continue;
            float dv = (flags & FL_DINV) ? g_dinv[m] : 1.f;
            #pragma unroll
            for (int nt = 0; nt < 8; nt++) {
                int col = wn + nt * 8 + 2 * tig;
                float vx = f.c[mt][nt][half * 2 + 0];
                float vy = f.c[mt][nt][half * 2 + 1];
                if (bias) {
                    float2 b2 = __ldg((const float2*)&bias[col]);
                    vx += b2.x; vy += b2.y;
                }
                if (flags & FL_DINV) { vx *= dv; vy *= dv; }
                if (flags & FL_RELU) { vx = fmaxf(vx, 0.f); vy = fmaxf(vy, 0.f); }
                __half2 hv = __floats2half2_rn(vx, vy);
                *(__half2*)&outp[(size_t)m * HH + col] = hv;
            }
        }
    }
}

// ---------------- pooling (fp16 input) + fused finalize ----------------
__global__ void k_pool2(const int* __restrict__ batch) {
    const __half* h = g_h3;
    int c = threadIdx.x;
    int n0 = blockIdx.x * 64;
    int n1 = n0 + 64; if (n1 > NN) n1 = NN;
    if (n0 >= NN) return;
    float acc = 0.f;
    int cur = __ldg(&batch[n0]);
    for (int n = n0; n < n1; n++) {
        int b = __ldg(&batch[n]);
        if (b != cur) { atomicAdd(&g_pool[cur * HH + c], acc); acc = 0.f; cur = b; }
        acc += __half2float(__ldg(&h[(size_t)n * HH + c]));
    }
    atomicAdd(&g_pool[cur * HH + c], acc);
}

// lower_bound on sorted batch: first i with batch[i] >= val
__device__ __forceinline__ int lb_batch(const int* __restrict__ batch, int val) {
    int lo = 0, hi = NN;
    while (lo < hi) {
        int mid = (lo + hi) >> 1;
        if (__ldg(&batch[mid]) < val) lo = mid + 1; else hi = mid;
    }
    return lo;
}

__global__ void k_final(const int* __restrict__ batch,
                        const float* __restrict__ Wl, const float* __restrict__ bl,
                        float* __restrict__ dout) {
    __shared__ float ws[4];
    __shared__ float xs[HH];
    __shared__ float winv[CC];
    int g = blockIdx.x, t = threadIdx.x;
    int cnt = lb_batch(batch, g + 1) - lb_batch(batch, g);
    float c = fmaxf((float)cnt, 1.f);
    float v = g_pool[g * HH + t] / c;
    float s = v * v;
    #pragma unroll
    for (int o = 16; o > 0; o >>= 1) s += __shfl_down_sync(0xFFFFFFFFu, s, o);
    if ((t & 31) == 0) ws[t >> 5] = s;
    if (t < CC) {
        float sw = 0.f;
        #pragma unroll 8
        for (int k = 0; k < HH; k++) { float w = __ldg(&Wl[t * HH + k]); sw = fmaf(w, w, sw); }
        winv[t] = 1.f / fmaxf(sqrtf(sw), 1e-12f);
    }
    __syncthreads();
    float tot = ws[0] + ws[1] + ws[2] + ws[3];
    float nrm = fmaxf(sqrtf(tot), 1e-12f);
    float xn = v / nrm;
    dout[g * HH + t] = xn;
    xs[t] = xn;
    __syncthreads();
    if (t < CC) {
        float s2 = 0.f;
        #pragma unroll 8
        for (int k = 0; k < HH; k++) s2 = fmaf(xs[k], __ldg(&Wl[t * HH + k]), s2);
        dout[GG * HH + g * CC + t] = fmaf(s2, winv[t], bl[t]);
    }
}

// ---------------- launch ----------------
extern "C" void kernel_launch(void* const* d_in, const int* in_sizes, int n_in,
                              void* d_out, int out_size) {
    const float* x    = (const float*)d_in[0];
    const int*   ei   = (const int*)d_in[1];
    const int*   batch= (const int*)d_in[2];
    const float* W1r  = (const float*)d_in[3];
    const float* b1   = (const float*)d_in[4];
    const float* W1x  = (const float*)d_in[5];
    const float* W2   = (const float*)d_in[6];
    const float* b2   = (const float*)d_in[7];
    const float* W3   = (const float*)d_in[8];
    const float* b3   = (const float*)d_in[9];
    const float* Wl   = (const float*)d_in[10];
    const float* bl   = (const float*)d_in[11];
    const int* row = ei;
    const int* col = ei + EE;
    float* out = (float*)d_out;

    cudaFuncSetAttribute(k_gemm, cudaFuncAttributeMaxDynamicSharedMemorySize, GEMM_SMEM);

    __half *xh, *agg, *h1, *h2, *hq;
    cudaGetSymbolAddress((void**)&xh, g_xh);
    cudaGetSymbolAddress((void**)&agg, g_agg);
    cudaGetSymbolAddress((void**)&h1, g_h1);
    cudaGetSymbolAddress((void**)&h2, g_h2);
    cudaGetSymbolAddress((void**)&hq, g_hq);

    // preprocessing (4 launches)
    k_zero_conv<<<(NN * HH / 4 + 255) / 256, 256>>>((const float4*)x, W1r, W1x, W2, W3);
    k_deg<<<(EE + 255) / 256, 256>>>(col);
    k_scan1<<<SCAN_BLK, 1024>>>();
    k_fill<<<(EE + 255) / 256, 256>>>(row, col);

    int AGG_GRID = (NN + 15) / 16;
    int GB = (NN + 127) / 128;

    // conv1 (fused): h1 = relu(agg@W1r^T + x@W1x^T + b1) -> fp16
    k_agg1<<<AGG_GRID, 256>>>();
    k_gemm<<<GB, 256, GEMM_SMEM>>>(agg, 0, xh, 1, b1, FL_RELU, h1);

    // conv2: hq2 = (h1@W2^T)*dinv -> fp16; h2 = relu(dinv*(sum)+b2) -> fp16
    k_gemm<<<GB, 256, GEMM_SMEM>>>(h1, 2, nullptr, 0, nullptr, FL_DINV, hq);
    k_aggn<<<AGG_GRID, 256>>>(b2, 1, 1);

    // conv3: hq3 = (h2@W3^T)*dinv -> fp16; h3 = dinv*(sum)+b3 -> fp16 g_h3
    k_gemm<<<GB, 256, GEMM_SMEM>>>(h2, 3, nullptr, 0, nullptr, FL_DINV, hq);
    k_aggn<<<AGG_GRID, 256>>>(b3, 0, 0);

    // pooling + normalize + classifier
    k_pool2<<<(NN + 63) / 64, 128>>>(batch);
    k_final<<<GG, HH>>>(batch, Wl, bl, out);
}

// round 14
// speedup vs baseline: 1.8040x; 1.0723x over previous
#include <cuda_runtime.h>
#include <cuda_fp16.h>
#include <math.h>
#include <cstdint>

#define NN 50000
#define EE 800000
#define HH 128
#define GG 128
#define CC 10
#define SCAN_BLK 49   // ceil(50000/1024)

// ---------------- static device scratch ----------------
__device__ int      g_deg[NN];
__device__ int      g_starts[NN + 1];
__device__ int      g_part[SCAN_BLK];
__device__ int      g_cursor[NN];
__device__ int      g_src[EE];
__device__ float    g_dinv[NN];
__device__ __half   g_xh[(size_t)NN * HH];   // fp16 x
__device__ __half   g_agg[(size_t)NN * HH];  // fp16 aggregated x
__device__ __half   g_h1[(size_t)NN * HH];   // fp16 h1
__device__ __half   g_h2[(size_t)NN * HH];   // fp16 h2
__device__ __half   g_hq[(size_t)NN * HH];   // fp16 hq (conv2/3 GEMM out)
__device__ __half   g_h3[(size_t)NN * HH];   // fp16 h3 for pooling
__device__ __half   g_WcH[4 * HH * HH];      // fp16 weights hi
__device__ __half   g_WcL[4 * HH * HH];      // fp16 weights lo (residual)
__device__ float    g_pool[GG * HH];

// ---------------- fused zero + conversions ----------------
__global__ void k_zero_conv(const float4* __restrict__ x4,
                            const float* __restrict__ W0, const float* __restrict__ W1,
                            const float* __restrict__ W2, const float* __restrict__ W3) {
    int p = blockIdx.x * blockDim.x + threadIdx.x;
    if (p < NN) g_deg[p] = 0;
    if (p < GG * HH) g_pool[p] = 0.f;
    if (p < NN * HH / 4) {
        float4 v = __ldg(&x4[p]);
        __half2 a = __floats2half2_rn(v.x, v.y);
        __half2 b = __floats2half2_rn(v.z, v.w);
        uint2 o; o.x = *(uint32_t*)&a; o.y = *(uint32_t*)&b;
        *(uint2*)&g_xh[(size_t)p * 4] = o;
    }
    if (p < HH * HH) {
        const float* Ws[4] = {W0, W1, W2, W3};
        #pragma unroll
        for (int w = 0; w < 4; w++) {
            float v = __ldg(&Ws[w][p]);
            __half h = __float2half(v);
            g_WcH[w * HH * HH + p] = h;
            g_WcL[w * HH * HH + p] = __float2half(v - __half2float(h));
        }
    }
}

__global__ void k_deg(const int* __restrict__ col) {
    int e = blockIdx.x * blockDim.x + threadIdx.x;
    if (e < EE) atomicAdd(&g_deg[col[e]], 1);
}

// ---- scan phase 1: per-block exclusive scan + block totals ----
__global__ void k_part() {
    __shared__ int warp_sums[32];
    int tid = threadIdx.x;
    int lane = tid & 31, wid = tid >> 5;
    int i = blockIdx.x * 1024 + tid;
    int v = (i < NN) ? g_deg[i] : 0;
    int s = v;
    #pragma unroll
    for (int o = 1; o < 32; o <<= 1) {
        int t = __shfl_up_sync(0xFFFFFFFFu, s, o);
        if (lane >= o) s += t;
    }
    if (lane == 31) warp_sums[wid] = s;
    __syncthreads();
    if (wid == 0) {
        int ws = warp_sums[lane];
        #pragma unroll
        for (int o = 1; o < 32; o <<= 1) {
            int t = __shfl_up_sync(0xFFFFFFFFu, ws, o);
            if (lane >= o) ws += t;
        }
        warp_sums[lane] = ws;
    }
    __syncthreads();
    int offset = (wid > 0) ? warp_sums[wid - 1] : 0;
    if (i < NN) g_starts[i] = offset + s - v;
    if (tid == 1023) g_part[blockIdx.x] = offset + s;
}

// ---- scan phase 2 fused: block-offset add + dinv + cursor ----
__global__ void k_addoff2() {
    __shared__ int s_part[SCAN_BLK];
    int tid = threadIdx.x, bid = blockIdx.x;
    if (tid < SCAN_BLK) s_part[tid] = g_part[tid];
    __syncthreads();
    int off = 0;
    for (int j = 0; j < bid; j++) off += s_part[j];
    int i = bid * 1024 + tid;
    if (i < NN) {
        int st = g_starts[i] + off;
        g_starts[i] = st;
        g_cursor[i] = st;
        g_dinv[i] = rsqrtf((float)(g_deg[i] + 1));
    }
    if (bid == SCAN_BLK - 1 && tid == 0)
        g_starts[NN] = off + s_part[SCAN_BLK - 1];
}

__global__ void k_fill(const int* __restrict__ row, const int* __restrict__ col) {
    int e = blockIdx.x * blockDim.x + threadIdx.x;
    if (e < EE) {
        int c = col[e];
        int p = atomicAdd(&g_cursor[c], 1);
        g_src[p] = row[e];
    }
}

// ---------------- aggregation (half-warp per node, uint4 lanes) ----------------
__device__ __forceinline__ void acc_half4(float4& acc, uint32_t lo, uint32_t hi) {
    float2 fa = __half22float2(*(__half2*)&lo);
    float2 fb = __half22float2(*(__half2*)&hi);
    acc.x += fa.x; acc.y += fa.y; acc.z += fb.x; acc.w += fb.y;
}
__device__ __forceinline__ void store_half8(__half* dst, size_t idx, float4 a, float4 b) {
    __half2 h0 = __floats2half2_rn(a.x, a.y);
    __half2 h1 = __floats2half2_rn(a.z, a.w);
    __half2 h2 = __floats2half2_rn(b.x, b.y);
    __half2 h3 = __floats2half2_rn(b.z, b.w);
    uint4 o;
    o.x = *(uint32_t*)&h0; o.y = *(uint32_t*)&h1;
    o.z = *(uint32_t*)&h2; o.w = *(uint32_t*)&h3;
    *(uint4*)&dst[idx] = o;
}

// gather x (fp16) -> g_agg; 2 nodes/warp, 16 lanes x 16B per row
__global__ void k_agg1() {
    int node = blockIdx.x * 16 + (threadIdx.x >> 4);
    if (node >= NN) return;
    int sub = threadIdx.x & 15;
    const uint4* xh = (const uint4*)g_xh;
    float4 acc0 = make_float4(0.f, 0.f, 0.f, 0.f);
    float4 acc1 = make_float4(0.f, 0.f, 0.f, 0.f);
    int s = g_starts[node], e = g_starts[node + 1];
    #pragma unroll 8
    for (int j = s; j < e; j++) {
        int u = __ldg(&g_src[j]);
        uint4 v = __ldg(&xh[(size_t)u * 16 + sub]);
        acc_half4(acc0, v.x, v.y);
        acc_half4(acc1, v.z, v.w);
    }
    store_half8(g_agg, (size_t)node * HH + sub * 8, acc0, acc1);
}

// gather g_hq (fp16), self+neigh, *dinv, +bias, optional relu; fp16 out
__global__ void k_aggn(const float* __restrict__ bias, int relu, int mode) {
    int node = blockIdx.x * 16 + (threadIdx.x >> 4);
    if (node >= NN) return;
    int sub = threadIdx.x & 15;
    const uint4* hq = (const uint4*)g_hq;
    float4 acc0 = make_float4(0.f, 0.f, 0.f, 0.f);
    float4 acc1 = make_float4(0.f, 0.f, 0.f, 0.f);
    {
        uint4 v = __ldg(&hq[(size_t)node * 16 + sub]);  // self
        acc_half4(acc0, v.x, v.y);
        acc_half4(acc1, v.z, v.w);
    }
    int s = g_starts[node], e = g_starts[node + 1];
    #pragma unroll 8
    for (int j = s; j < e; j++) {
        int u = __ldg(&g_src[j]);
        uint4 v = __ldg(&hq[(size_t)u * 16 + sub]);
        acc_half4(acc0, v.x, v.y);
        acc_half4(acc1, v.z, v.w);
    }
    float dv = g_dinv[node];
    float4 b0 = __ldg(&((const float4*)bias)[sub * 2]);
    float4 b1 = __ldg(&((const float4*)bias)[sub * 2 + 1]);
    float4 r0, r1;
    r0.x = fmaf(acc0.x, dv, b0.x); r0.y = fmaf(acc0.y, dv, b0.y);
    r0.z = fmaf(acc0.z, dv, b0.z); r0.w = fmaf(acc0.w, dv, b0.w);
    r1.x = fmaf(acc1.x, dv, b1.x); r1.y = fmaf(acc1.y, dv, b1.y);
    r1.z = fmaf(acc1.z, dv, b1.z); r1.w = fmaf(acc1.w, dv, b1.w);
    if (relu) {
        r0.x = fmaxf(r0.x, 0.f); r0.y = fmaxf(r0.y, 0.f);
        r0.z = fmaxf(r0.z, 0.f); r0.w = fmaxf(r0.w, 0.f);
        r1.x = fmaxf(r1.x, 0.f); r1.y = fmaxf(r1.y, 0.f);
        r1.z = fmaxf(r1.z, 0.f); r1.w = fmaxf(r1.w, 0.f);
    }
    if (mode) {
        store_half8(g_h2, (size_t)node * HH + sub * 8, r0, r1);
    } else {
        store_half8(g_h3, (size_t)node * HH + sub * 8, r0, r1);
    }
}

// ---------------- HMMA GEMM (fp16 A, split-fp16 W, ldmatrix) ----------------
#define FL_RELU 2
#define FL_DINV 4
#define APITCH 136
#define GEMM_SMEM (3 * 128 * APITCH * 2)

__device__ __forceinline__ uint32_t smem_u32(const void* p) {
    uint32_t a;
    asm("{ .reg .u64 t; cvta.to.shared.u64 t, %1; cvt.u32.u64 %0, t; }" : "=r"(a) : "l"(p));
    return a;
}
__device__ __forceinline__ void ldsm_x4(uint32_t& r0, uint32_t& r1, uint32_t& r2, uint32_t& r3,
                                        uint32_t addr) {
    asm volatile("ldmatrix.sync.aligned.m8n8.x4.shared.b16 {%0,%1,%2,%3}, [%4];"
        : "=r"(r0), "=r"(r1), "=r"(r2), "=r"(r3) : "r"(addr));
}
__device__ __forceinline__ void mma16816(float* c, const uint32_t* a, uint32_t b0, uint32_t b1) {
    asm volatile("mma.sync.aligned.m16n8k16.row.col.f32.f16.f16.f32 "
        "{%0,%1,%2,%3}, {%4,%5,%6,%7}, {%8,%9}, {%0,%1,%2,%3};"
        : "+f"(c[0]), "+f"(c[1]), "+f"(c[2]), "+f"(c[3])
        : "r"(a[0]), "r"(a[1]), "r"(a[2]), "r"(a[3]), "r"(b0), "r"(b1));
}

// copy fp16 tile [128 x 128] global -> padded smem (16B vectors)
__device__ __forceinline__ void load_tile16(__half* dst, const __half* src, int m0,
                                            int bound, int tid) {
    const uint4* s4 = (const uint4*)src;
    #pragma unroll 2
    for (int p = tid; p < 2048; p += 256) {
        int row = p >> 4, c8 = p & 15;
        int m = m0 + row;
        uint4 v = make_uint4(0u, 0u, 0u, 0u);
        if (m < bound) v = __ldg(&s4[(size_t)m * 16 + c8]);
        *(uint4*)&dst[row * APITCH + c8 * 8] = v;
    }
}

struct Frag { float c[2][8][4]; };

// one stage-pair: f += A*Wh^T + A*Wl^T
__device__ __forceinline__ void mma_stage2(Frag& f, uint32_t aBase, uint32_t whBase,
                                           uint32_t wlBase, int wm, int wn, int lane) {
    int lr = lane & 7, q = lane >> 3;
    int arow = wm + ((q & 1) << 3) + lr;
    int acol = (q >> 1) << 3;
    int brow = wn + ((q >> 1) << 3) + lr;
    int bcol = (q & 1) << 3;
    #pragma unroll
    for (int ks = 0; ks < 8; ks++) {
        int kb0 = ks * 16;
        uint32_t a[2][4];
        #pragma unroll
        for (int mt = 0; mt < 2; mt++) {
            uint32_t addr = aBase + (uint32_t)(((arow + mt * 16) * APITCH + kb0 + acol) * 2);
            ldsm_x4(a[mt][0], a[mt][1], a[mt][2], a[mt][3], addr);
        }
        #pragma unroll
        for (int pass = 0; pass < 2; pass++) {
            uint32_t wBase = pass ? wlBase : whBase;
            #pragma unroll
            for (int ntp = 0; ntp < 4; ntp++) {
                uint32_t addr = wBase + (uint32_t)(((brow + ntp * 16) * APITCH + kb0 + bcol) * 2);
                uint32_t b0e, b1e, b0o, b1o;
                ldsm_x4(b0e, b1e, b0o, b1o, addr);
                mma16816(f.c[0][2 * ntp],     a[0], b0e, b1e);
                mma16816(f.c[1][2 * ntp],     a[1], b0e, b1e);
                mma16816(f.c[0][2 * ntp + 1], a[0], b0o, b1o);
                mma16816(f.c[1][2 * ntp + 1], a[1], b0o, b1o);
            }
        }
    }
}

// C[M,128] = A@W[w0]^T (+ A2@W[w1]^T) (+bias) (*dinv) (relu) -> fp16 out
__global__ __launch_bounds__(256, 2) void k_gemm(
    const __half* __restrict__ A, int w0,
    const __half* __restrict__ A2, int w1,
    const float* __restrict__ bias, int flags,
    __half* __restrict__ outp)
{
    extern __shared__ __half sm[];
    __half* Ah = sm;
    __half* Wh = Ah + 128 * APITCH;
    __half* Wl = Wh + 128 * APITCH;
    int tid = threadIdx.x, wid = tid >> 5, lane = tid & 31;
    int m0 = blockIdx.x * 128;
    int wm = (wid & 3) * 32;
    int wn = (wid >> 2) * 64;
    int g = lane >> 2, tig = lane & 3;
    uint32_t aBase = smem_u32(Ah), whBase = smem_u32(Wh), wlBase = smem_u32(Wl);

    Frag f;
    #pragma unroll
    for (int mt = 0; mt < 2; mt++)
        #pragma unroll
        for (int nt = 0; nt < 8; nt++)
            #pragma unroll
            for (int j = 0; j < 4; j++) f.c[mt][nt][j] = 0.f;

    load_tile16(Ah, A, m0, NN, tid);
    load_tile16(Wh, g_WcH + (size_t)w0 * HH * HH, 0, HH, tid);
    load_tile16(Wl, g_WcL + (size_t)w0 * HH * HH, 0, HH, tid);
    __syncthreads();
    mma_stage2(f, aBase, whBase, wlBase, wm, wn, lane);

    if (A2) {
        __syncthreads();
        load_tile16(Ah, A2, m0, NN, tid);
        load_tile16(Wh, g_WcH + (size_t)w1 * HH * HH, 0, HH, tid);
        load_tile16(Wl, g_WcL + (size_t)w1 * HH * HH, 0, HH, tid);
        __syncthreads();
        mma_stage2(f, aBase, whBase, wlBase, wm, wn, lane);
    }

    #pragma unroll
    for (int mt = 0; mt < 2; mt++) {
        #pragma unroll
        for (int half = 0; half < 2; half++) {
            int m = m0 + wm + mt * 16 + g + half * 8;
            if (m >= NN) continue;
            float dv = (flags & FL_DINV) ? g_dinv[m] : 1.f;
            #pragma unroll
            for (int nt = 0; nt < 8; nt++) {
                int col = wn + nt * 8 + 2 * tig;
                float vx = f.c[mt][nt][half * 2 + 0];
                float vy = f.c[mt][nt][half * 2 + 1];
                if (bias) {
                    float2 b2 = __ldg((const float2*)&bias[col]);
                    vx += b2.x; vy += b2.y;
                }
                if (flags & FL_DINV) { vx *= dv; vy *= dv; }
                if (flags & FL_RELU) { vx = fmaxf(vx, 0.f); vy = fmaxf(vy, 0.f); }
                __half2 hv = __floats2half2_rn(vx, vy);
                *(__half2*)&outp[(size_t)m * HH + col] = hv;
            }
        }
    }
}

// ---------------- pooling (fp16 input) + fused finalize ----------------
__global__ void k_pool2(const int* __restrict__ batch) {
    const __half* h = g_h3;
    int c = threadIdx.x;
    int n0 = blockIdx.x * 64;
    int n1 = n0 + 64; if (n1 > NN) n1 = NN;
    if (n0 >= NN) return;
    float acc = 0.f;
    int cur = __ldg(&batch[n0]);
    for (int n = n0; n < n1; n++) {
        int b = __ldg(&batch[n]);
        if (b != cur) { atomicAdd(&g_pool[cur * HH + c], acc); acc = 0.f; cur = b; }
        acc += __half2float(__ldg(&h[(size_t)n * HH + c]));
    }
    atomicAdd(&g_pool[cur * HH + c], acc);
}

// lower_bound on sorted batch: first i with batch[i] >= val
__device__ __forceinline__ int lb_batch(const int* __restrict__ batch, int val) {
    int lo = 0, hi = NN;
    while (lo < hi) {
        int mid = (lo + hi) >> 1;
        if (__ldg(&batch[mid]) < val) lo = mid + 1; else hi = mid;
    }
    return lo;
}

__global__ void k_final(const int* __restrict__ batch,
                        const float* __restrict__ Wl, const float* __restrict__ bl,
                        float* __restrict__ dout) {
    __shared__ float ws[4];
    __shared__ float xs[HH];
    __shared__ float winv[CC];
    int g = blockIdx.x, t = threadIdx.x;
    int cnt = lb_batch(batch, g + 1) - lb_batch(batch, g);
    float c = fmaxf((float)cnt, 1.f);
    float v = g_pool[g * HH + t] / c;
    float s = v * v;
    #pragma unroll
    for (int o = 16; o > 0; o >>= 1) s += __shfl_down_sync(0xFFFFFFFFu, s, o);
    if ((t & 31) == 0) ws[t >> 5] = s;
    if (t < CC) {
        float sw = 0.f;
        #pragma unroll 8
        for (int k = 0; k < HH; k++) { float w = __ldg(&Wl[t * HH + k]); sw = fmaf(w, w, sw); }
        winv[t] = 1.f / fmaxf(sqrtf(sw), 1e-12f);
    }
    __syncthreads();
    float tot = ws[0] + ws[1] + ws[2] + ws[3];
    float nrm = fmaxf(sqrtf(tot), 1e-12f);
    float xn = v / nrm;
    dout[g * HH + t] = xn;
    xs[t] = xn;
    __syncthreads();
    if (t < CC) {
        float s2 = 0.f;
        #pragma unroll 8
        for (int k = 0; k < HH; k++) s2 = fmaf(xs[k], __ldg(&Wl[t * HH + k]), s2);
        dout[GG * HH + g * CC + t] = fmaf(s2, winv[t], bl[t]);
    }
}

// ---------------- launch ----------------
extern "C" void kernel_launch(void* const* d_in, const int* in_sizes, int n_in,
                              void* d_out, int out_size) {
    const float* x    = (const float*)d_in[0];
    const int*   ei   = (const int*)d_in[1];
    const int*   batch= (const int*)d_in[2];
    const float* W1r  = (const float*)d_in[3];
    const float* b1   = (const float*)d_in[4];
    const float* W1x  = (const float*)d_in[5];
    const float* W2   = (const float*)d_in[6];
    const float* b2   = (const float*)d_in[7];
    const float* W3   = (const float*)d_in[8];
    const float* b3   = (const float*)d_in[9];
    const float* Wl   = (const float*)d_in[10];
    const float* bl   = (const float*)d_in[11];
    const int* row = ei;
    const int* col = ei + EE;
    float* out = (float*)d_out;

    cudaFuncSetAttribute(k_gemm, cudaFuncAttributeMaxDynamicSharedMemorySize, GEMM_SMEM);

    __half *xh, *agg, *h1, *h2, *hq;
    cudaGetSymbolAddress((void**)&xh, g_xh);
    cudaGetSymbolAddress((void**)&agg, g_agg);
    cudaGetSymbolAddress((void**)&h1, g_h1);
    cudaGetSymbolAddress((void**)&h2, g_h2);
    cudaGetSymbolAddress((void**)&hq, g_hq);

    // preprocessing
    k_zero_conv<<<(NN * HH / 4 + 255) / 256, 256>>>((const float4*)x, W1r, W1x, W2, W3);
    k_deg<<<(EE + 255) / 256, 256>>>(col);
    k_part<<<SCAN_BLK, 1024>>>();
    k_addoff2<<<SCAN_BLK, 1024>>>();
    k_fill<<<(EE + 255) / 256, 256>>>(row, col);

    int AGG_GRID = (NN + 15) / 16;
    int GB = (NN + 127) / 128;

    // conv1 (fused): h1 = relu(agg@W1r^T + x@W1x^T + b1) -> fp16
    k_agg1<<<AGG_GRID, 256>>>();
    k_gemm<<<GB, 256, GEMM_SMEM>>>(agg, 0, xh, 1, b1, FL_RELU, h1);

    // conv2: hq2 = (h1@W2^T)*dinv -> fp16; h2 = relu(dinv*(sum)+b2) -> fp16
    k_gemm<<<GB, 256, GEMM_SMEM>>>(h1, 2, nullptr, 0, nullptr, FL_DINV, hq);
    k_aggn<<<AGG_GRID, 256>>>(b2, 1, 1);

    // conv3: hq3 = (h2@W3^T)*dinv -> fp16; h3 = dinv*(sum)+b3 -> fp16 g_h3
    k_gemm<<<GB, 256, GEMM_SMEM>>>(h2, 3, nullptr, 0, nullptr, FL_DINV, hq);
    k_aggn<<<AGG_GRID, 256>>>(b3, 0, 0);

    // pooling + normalize + classifier
    k_pool2<<<(NN + 63) / 64, 128>>>(batch);
    k_final<<<GG, HH>>>(batch, Wl, bl, out);
}

// round 15
// speedup vs baseline: 1.8078x; 1.0021x over previous
#include <cuda_runtime.h>
#include <cuda_fp16.h>
#include <math.h>
#include <cstdint>

#define NN 50000
#define EE 800000
#define HH 128
#define GG 128
#define CC 10
#define SCAN_BLK 49   // ceil(50000/1024)

// ---------------- static device scratch ----------------
__device__ int      g_deg[NN];
__device__ int      g_starts[NN + 1];
__device__ int      g_part[SCAN_BLK];
__device__ int      g_cursor[NN];
__device__ int      g_src[EE];
__device__ float    g_dinv[NN];
__device__ __half   g_xh[(size_t)NN * HH];   // fp16 x
__device__ __half   g_agg[(size_t)NN * HH];  // fp16 aggregated x
__device__ __half   g_h1[(size_t)NN * HH];   // fp16 h1
__device__ __half   g_h2[(size_t)NN * HH];   // fp16 h2
__device__ __half   g_hq[(size_t)NN * HH];   // fp16 hq (conv2/3 GEMM out)
__device__ __half   g_h3[(size_t)NN * HH];   // fp16 h3 for pooling
__device__ __half   g_WcH[4 * HH * HH];      // fp16 weights hi
__device__ __half   g_WcL[4 * HH * HH];      // fp16 weights lo (residual)
__device__ float    g_pool[GG * HH];

// ---------------- fused zero + conversions ----------------
__global__ void k_zero_conv(const float4* __restrict__ x4,
                            const float* __restrict__ W0, const float* __restrict__ W1,
                            const float* __restrict__ W2, const float* __restrict__ W3) {
    int p = blockIdx.x * blockDim.x + threadIdx.x;
    if (p < NN) g_deg[p] = 0;
    if (p < GG * HH) g_pool[p] = 0.f;
    if (p < NN * HH / 4) {
        float4 v = __ldg(&x4[p]);
        __half2 a = __floats2half2_rn(v.x, v.y);
        __half2 b = __floats2half2_rn(v.z, v.w);
        uint2 o; o.x = *(uint32_t*)&a; o.y = *(uint32_t*)&b;
        *(uint2*)&g_xh[(size_t)p * 4] = o;
    }
    if (p < HH * HH) {
        const float* Ws[4] = {W0, W1, W2, W3};
        #pragma unroll
        for (int w = 0; w < 4; w++) {
            float v = __ldg(&Ws[w][p]);
            __half h = __float2half(v);
            g_WcH[w * HH * HH + p] = h;
            g_WcL[w * HH * HH + p] = __float2half(v - __half2float(h));
        }
    }
}

// degree count: 4 edges per thread (MLP=4 on the atomics)
__global__ void k_deg(const int4* __restrict__ col4) {
    int t = blockIdx.x * blockDim.x + threadIdx.x;
    if (t < EE / 4) {
        int4 c = __ldg(&col4[t]);
        atomicAdd(&g_deg[c.x], 1);
        atomicAdd(&g_deg[c.y], 1);
        atomicAdd(&g_deg[c.z], 1);
        atomicAdd(&g_deg[c.w], 1);
    }
}

// ---- scan phase 1: per-block exclusive scan + block totals ----
__global__ void k_part() {
    __shared__ int warp_sums[32];
    int tid = threadIdx.x;
    int lane = tid & 31, wid = tid >> 5;
    int i = blockIdx.x * 1024 + tid;
    int v = (i < NN) ? g_deg[i] : 0;
    int s = v;
    #pragma unroll
    for (int o = 1; o < 32; o <<= 1) {
        int t = __shfl_up_sync(0xFFFFFFFFu, s, o);
        if (lane >= o) s += t;
    }
    if (lane == 31) warp_sums[wid] = s;
    __syncthreads();
    if (wid == 0) {
        int ws = warp_sums[lane];
        #pragma unroll
        for (int o = 1; o < 32; o <<= 1) {
            int t = __shfl_up_sync(0xFFFFFFFFu, ws, o);
            if (lane >= o) ws += t;
        }
        warp_sums[lane] = ws;
    }
    __syncthreads();
    int offset = (wid > 0) ? warp_sums[wid - 1] : 0;
    if (i < NN) g_starts[i] = offset + s - v;
    if (tid == 1023) g_part[blockIdx.x] = offset + s;
}

// ---- scan phase 2 fused: block-offset add + dinv + cursor ----
__global__ void k_addoff2() {
    __shared__ int s_part[SCAN_BLK];
    int tid = threadIdx.x, bid = blockIdx.x;
    if (tid < SCAN_BLK) s_part[tid] = g_part[tid];
    __syncthreads();
    int off = 0;
    for (int j = 0; j < bid; j++) off += s_part[j];
    int i = bid * 1024 + tid;
    if (i < NN) {
        int st = g_starts[i] + off;
        g_starts[i] = st;
        g_cursor[i] = st;
        g_dinv[i] = rsqrtf((float)(g_deg[i] + 1));
    }
    if (bid == SCAN_BLK - 1 && tid == 0)
        g_starts[NN] = off + s_part[SCAN_BLK - 1];
}

// CSR fill: 4 edges per thread (independent atomic+store chains)
__global__ void k_fill(const int4* __restrict__ row4, const int4* __restrict__ col4) {
    int t = blockIdx.x * blockDim.x + threadIdx.x;
    if (t < EE / 4) {
        int4 r = __ldg(&row4[t]);
        int4 c = __ldg(&col4[t]);
        int p0 = atomicAdd(&g_cursor[c.x], 1);
        int p1 = atomicAdd(&g_cursor[c.y], 1);
        int p2 = atomicAdd(&g_cursor[c.z], 1);
        int p3 = atomicAdd(&g_cursor[c.w], 1);
        g_src[p0] = r.x;
        g_src[p1] = r.y;
        g_src[p2] = r.z;
        g_src[p3] = r.w;
    }
}

// ---------------- aggregation (half-warp per node, uint4 lanes) ----------------
__device__ __forceinline__ void acc_half4(float4& acc, uint32_t lo, uint32_t hi) {
    float2 fa = __half22float2(*(__half2*)&lo);
    float2 fb = __half22float2(*(__half2*)&hi);
    acc.x += fa.x; acc.y += fa.y; acc.z += fb.x; acc.w += fb.y;
}
__device__ __forceinline__ void store_half8(__half* dst, size_t idx, float4 a, float4 b) {
    __half2 h0 = __floats2half2_rn(a.x, a.y);
    __half2 h1 = __floats2half2_rn(a.z, a.w);
    __half2 h2 = __floats2half2_rn(b.x, b.y);
    __half2 h3 = __floats2half2_rn(b.z, b.w);
    uint4 o;
    o.x = *(uint32_t*)&h0; o.y = *(uint32_t*)&h1;
    o.z = *(uint32_t*)&h2; o.w = *(uint32_t*)&h3;
    *(uint4*)&dst[idx] = o;
}

// gather x (fp16) -> g_agg; 2 nodes/warp, 16 lanes x 16B per row
__global__ void k_agg1() {
    int node = blockIdx.x * 16 + (threadIdx.x >> 4);
    if (node >= NN) return;
    int sub = threadIdx.x & 15;
    const uint4* xh = (const uint4*)g_xh;
    float4 acc0 = make_float4(0.f, 0.f, 0.f, 0.f);
    float4 acc1 = make_float4(0.f, 0.f, 0.f, 0.f);
    int s = g_starts[node], e = g_starts[node + 1];
    #pragma unroll 8
    for (int j = s; j < e; j++) {
        int u = __ldg(&g_src[j]);
        uint4 v = __ldg(&xh[(size_t)u * 16 + sub]);
        acc_half4(acc0, v.x, v.y);
        acc_half4(acc1, v.z, v.w);
    }
    store_half8(g_agg, (size_t)node * HH + sub * 8, acc0, acc1);
}

// gather g_hq (fp16), self+neigh, *dinv, +bias, optional relu; fp16 out
__global__ void k_aggn(const float* __restrict__ bias, int relu, int mode) {
    int node = blockIdx.x * 16 + (threadIdx.x >> 4);
    if (node >= NN) return;
    int sub = threadIdx.x & 15;
    const uint4* hq = (const uint4*)g_hq;
    float4 acc0 = make_float4(0.f, 0.f, 0.f, 0.f);
    float4 acc1 = make_float4(0.f, 0.f, 0.f, 0.f);
    {
        uint4 v = __ldg(&hq[(size_t)node * 16 + sub]);  // self
        acc_half4(acc0, v.x, v.y);
        acc_half4(acc1, v.z, v.w);
    }
    int s = g_starts[node], e = g_starts[node + 1];
    #pragma unroll 8
    for (int j = s; j < e; j++) {
        int u = __ldg(&g_src[j]);
        uint4 v = __ldg(&hq[(size_t)u * 16 + sub]);
        acc_half4(acc0, v.x, v.y);
        acc_half4(acc1, v.z, v.w);
    }
    float dv = g_dinv[node];
    float4 b0 = __ldg(&((const float4*)bias)[sub * 2]);
    float4 b1 = __ldg(&((const float4*)bias)[sub * 2 + 1]);
    float4 r0, r1;
    r0.x = fmaf(acc0.x, dv, b0.x); r0.y = fmaf(acc0.y, dv, b0.y);
    r0.z = fmaf(acc0.z, dv, b0.z); r0.w = fmaf(acc0.w, dv, b0.w);
    r1.x = fmaf(acc1.x, dv, b1.x); r1.y = fmaf(acc1.y, dv, b1.y);
    r1.z = fmaf(acc1.z, dv, b1.z); r1.w = fmaf(acc1.w, dv, b1.w);
    if (relu) {
        r0.x = fmaxf(r0.x, 0.f); r0.y = fmaxf(r0.y, 0.f);
        r0.z = fmaxf(r0.z, 0.f); r0.w = fmaxf(r0.w, 0.f);
        r1.x = fmaxf(r1.x, 0.f); r1.y = fmaxf(r1.y, 0.f);
        r1.z = fmaxf(r1.z, 0.f); r1.w = fmaxf(r1.w, 0.f);
    }
    if (mode) {
        store_half8(g_h2, (size_t)node * HH + sub * 8, r0, r1);
    } else {
        store_half8(g_h3, (size_t)node * HH + sub * 8, r0, r1);
    }
}

// ---------------- HMMA GEMM (fp16 A, split-fp16 W, ldmatrix) ----------------
#define FL_RELU 2
#define FL_DINV 4
#define APITCH 136
#define GEMM_SMEM (3 * 128 * APITCH * 2)

__device__ __forceinline__ uint32_t smem_u32(const void* p) {
    uint32_t a;
    asm("{ .reg .u64 t; cvta.to.shared.u64 t, %1; cvt.u32.u64 %0, t; }" : "=r"(a) : "l"(p));
    return a;
}
__device__ __forceinline__ void ldsm_x4(uint32_t& r0, uint32_t& r1, uint32_t& r2, uint32_t& r3,
                                        uint32_t addr) {
    asm volatile("ldmatrix.sync.aligned.m8n8.x4.shared.b16 {%0,%1,%2,%3}, [%4];"
        : "=r"(r0), "=r"(r1), "=r"(r2), "=r"(r3) : "r"(addr));
}
__device__ __forceinline__ void mma16816(float* c, const uint32_t* a, uint32_t b0, uint32_t b1) {
    asm volatile("mma.sync.aligned.m16n8k16.row.col.f32.f16.f16.f32 "
        "{%0,%1,%2,%3}, {%4,%5,%6,%7}, {%8,%9}, {%0,%1,%2,%3};"
        : "+f"(c[0]), "+f"(c[1]), "+f"(c[2]), "+f"(c[3])
        : "r"(a[0]), "r"(a[1]), "r"(a[2]), "r"(a[3]), "r"(b0), "r"(b1));
}

// copy fp16 tile [128 x 128] global -> padded smem (16B vectors)
__device__ __forceinline__ void load_tile16(__half* dst, const __half* src, int m0,
                                            int bound, int tid) {
    const uint4* s4 = (const uint4*)src;
    #pragma unroll 2
    for (int p = tid; p < 2048; p += 256) {
        int row = p >> 4, c8 = p & 15;
        int m = m0 + row;
        uint4 v = make_uint4(0u, 0u, 0u, 0u);
        if (m < bound) v = __ldg(&s4[(size_t)m * 16 + c8]);
        *(uint4*)&dst[row * APITCH + c8 * 8] = v;
    }
}

struct Frag { float c[2][8][4]; };

// one stage-pair: f += A*Wh^T + A*Wl^T
__device__ __forceinline__ void mma_stage2(Frag& f, uint32_t aBase, uint32_t whBase,
                                           uint32_t wlBase, int wm, int wn, int lane) {
    int lr = lane & 7, q = lane >> 3;
    int arow = wm + ((q & 1) << 3) + lr;
    int acol = (q >> 1) << 3;
    int brow = wn + ((q >> 1) << 3) + lr;
    int bcol = (q & 1) << 3;
    #pragma unroll
    for (int ks = 0; ks < 8; ks++) {
        int kb0 = ks * 16;
        uint32_t a[2][4];
        #pragma unroll
        for (int mt = 0; mt < 2; mt++) {
            uint32_t addr = aBase + (uint32_t)(((arow + mt * 16) * APITCH + kb0 + acol) * 2);
            ldsm_x4(a[mt][0], a[mt][1], a[mt][2], a[mt][3], addr);
        }
        #pragma unroll
        for (int pass = 0; pass < 2; pass++) {
            uint32_t wBase = pass ? wlBase : whBase;
            #pragma unroll
            for (int ntp = 0; ntp < 4; ntp++) {
                uint32_t addr = wBase + (uint32_t)(((brow + ntp * 16) * APITCH + kb0 + bcol) * 2);
                uint32_t b0e, b1e, b0o, b1o;
                ldsm_x4(b0e, b1e, b0o, b1o, addr);
                mma16816(f.c[0][2 * ntp],     a[0], b0e, b1e);
                mma16816(f.c[1][2 * ntp],     a[1], b0e, b1e);
                mma16816(f.c[0][2 * ntp + 1], a[0], b0o, b1o);
                mma16816(f.c[1][2 * ntp + 1], a[1], b0o, b1o);
            }
        }
    }
}

// C[M,128] = A@W[w0]^T (+ A2@W[w1]^T) (+bias) (*dinv) (relu) -> fp16 out
__global__ __launch_bounds__(256, 2) void k_gemm(
    const __half* __restrict__ A, int w0,
    const __half* __restrict__ A2, int w1,
    const float* __restrict__ bias, int flags,
    __half* __restrict__ outp)
{
    extern __shared__ __half sm[];
    __half* Ah = sm;
    __half* Wh = Ah + 128 * APITCH;
    __half* Wl = Wh + 128 * APITCH;
    int tid = threadIdx.x, wid = tid >> 5, lane = tid & 31;
    int m0 = blockIdx.x * 128;
    int wm = (wid & 3) * 32;
    int wn = (wid >> 2) * 64;
    int g = lane >> 2, tig = lane & 3;
    uint32_t aBase = smem_u32(Ah), whBase = smem_u32(Wh), wlBase = smem_u32(Wl);

    Frag f;
    #pragma unroll
    for (int mt = 0; mt < 2; mt++)
        #pragma unroll
        for (int nt = 0; nt < 8; nt++)
            #pragma unroll
            for (int j = 0; j < 4; j++) f.c[mt][nt][j] = 0.f;

    load_tile16(Ah, A, m0, NN, tid);
    load_tile16(Wh, g_WcH + (size_t)w0 * HH * HH, 0, HH, tid);
    load_tile16(Wl, g_WcL + (size_t)w0 * HH * HH, 0, HH, tid);
    __syncthreads();
    mma_stage2(f, aBase, whBase, wlBase, wm, wn, lane);

    if (A2) {
        __syncthreads();
        load_tile16(Ah, A2, m0, NN, tid);
        load_tile16(Wh, g_WcH + (size_t)w1 * HH * HH, 0, HH, tid);
        load_tile16(Wl, g_WcL + (size_t)w1 * HH * HH, 0, HH, tid);
        __syncthreads();
        mma_stage2(f, aBase, whBase, wlBase, wm, wn, lane);
    }

    #pragma unroll
    for (int mt = 0; mt < 2; mt++) {
        #pragma unroll
        for (int half = 0; half < 2; half++) {
            int m = m0 + wm + mt * 16 + g + half * 8;
            if (m >= NN) continue;
            float dv = (flags & FL_DINV) ? g_dinv[m] : 1.f;
            #pragma unroll
            for (int nt = 0; nt < 8; nt++) {
                int col = wn + nt * 8 + 2 * tig;
                float vx = f.c[mt][nt][half * 2 + 0];
                float vy = f.c[mt][nt][half * 2 + 1];
                if (bias) {
                    float2 b2 = __ldg((const float2*)&bias[col]);
                    vx += b2.x; vy += b2.y;
                }
                if (flags & FL_DINV) { vx *= dv; vy *= dv; }
                if (flags & FL_RELU) { vx = fmaxf(vx, 0.f); vy = fmaxf(vy, 0.f); }
                __half2 hv = __floats2half2_rn(vx, vy);
                *(__half2*)&outp[(size_t)m * HH + col] = hv;
            }
        }
    }
}

// ---------------- pooling (fp16 input) + fused finalize ----------------
__global__ void k_pool2(const int* __restrict__ batch) {
    const __half* h = g_h3;
    int c = threadIdx.x;
    int n0 = blockIdx.x * 64;
    int n1 = n0 + 64; if (n1 > NN) n1 = NN;
    if (n0 >= NN) return;
    float acc = 0.f;
    int cur = __ldg(&batch[n0]);
    for (int n = n0; n < n1; n++) {
        int b = __ldg(&batch[n]);
        if (b != cur) { atomicAdd(&g_pool[cur * HH + c], acc); acc = 0.f; cur = b; }
        acc += __half2float(__ldg(&h[(size_t)n * HH + c]));
    }
    atomicAdd(&g_pool[cur * HH + c], acc);
}

// lower_bound on sorted batch: first i with batch[i] >= val
__device__ __forceinline__ int lb_batch(const int* __restrict__ batch, int val) {
    int lo = 0, hi = NN;
    while (lo < hi) {
        int mid = (lo + hi) >> 1;
        if (__ldg(&batch[mid]) < val) lo = mid + 1; else hi = mid;
    }
    return lo;
}

__global__ void k_final(const int* __restrict__ batch,
                        const float* __restrict__ Wl, const float* __restrict__ bl,
                        float* __restrict__ dout) {
    __shared__ float ws[4];
    __shared__ float xs[HH];
    __shared__ float winv[CC];
    int g = blockIdx.x, t = threadIdx.x;
    int cnt = lb_batch(batch, g + 1) - lb_batch(batch, g);
    float c = fmaxf((float)cnt, 1.f);
    float v = g_pool[g * HH + t] / c;
    float s = v * v;
    #pragma unroll
    for (int o = 16; o > 0; o >>= 1) s += __shfl_down_sync(0xFFFFFFFFu, s, o);
    if ((t & 31) == 0) ws[t >> 5] = s;
    if (t < CC) {
        float sw = 0.f;
        #pragma unroll 8
        for (int k = 0; k < HH; k++) { float w = __ldg(&Wl[t * HH + k]); sw = fmaf(w, w, sw); }
        winv[t] = 1.f / fmaxf(sqrtf(sw), 1e-12f);
    }
    __syncthreads();
    float tot = ws[0] + ws[1] + ws[2] + ws[3];
    float nrm = fmaxf(sqrtf(tot), 1e-12f);
    float xn = v / nrm;
    dout[g * HH + t] = xn;
    xs[t] = xn;
    __syncthreads();
    if (t < CC) {
        float s2 = 0.f;
        #pragma unroll 8
        for (int k = 0; k < HH; k++) s2 = fmaf(xs[k], __ldg(&Wl[t * HH + k]), s2);
        dout[GG * HH + g * CC + t] = fmaf(s2, winv[t], bl[t]);
    }
}

// ---------------- launch ----------------
extern "C" void kernel_launch(void* const* d_in, const int* in_sizes, int n_in,
                              void* d_out, int out_size) {
    const float* x    = (const float*)d_in[0];
    const int*   ei   = (const int*)d_in[1];
    const int*   batch= (const int*)d_in[2];
    const float* W1r  = (const float*)d_in[3];
    const float* b1   = (const float*)d_in[4];
    const float* W1x  = (const float*)d_in[5];
    const float* W2   = (const float*)d_in[6];
    const float* b2   = (const float*)d_in[7];
    const float* W3   = (const float*)d_in[8];
    const float* b3   = (const float*)d_in[9];
    const float* Wl   = (const float*)d_in[10];
    const float* bl   = (const float*)d_in[11];
    const int* row = ei;
    const int* col = ei + EE;
    float* out = (float*)d_out;

    cudaFuncSetAttribute(k_gemm, cudaFuncAttributeMaxDynamicSharedMemorySize, GEMM_SMEM);

    __half *xh, *agg, *h1, *h2, *hq;
    cudaGetSymbolAddress((void**)&xh, g_xh);
    cudaGetSymbolAddress((void**)&agg, g_agg);
    cudaGetSymbolAddress((void**)&h1, g_h1);
    cudaGetSymbolAddress((void**)&h2, g_h2);
    cudaGetSymbolAddress((void**)&hq, g_hq);

    // preprocessing
    k_zero_conv<<<(NN * HH / 4 + 255) / 256, 256>>>((const float4*)x, W1r, W1x, W2, W3);
    k_deg<<<(EE / 4 + 255) / 256, 256>>>((const int4*)col);
    k_part<<<SCAN_BLK, 1024>>>();
    k_addoff2<<<SCAN_BLK, 1024>>>();
    k_fill<<<(EE / 4 + 255) / 256, 256>>>((const int4*)row, (const int4*)col);

    int AGG_GRID = (NN + 15) / 16;
    int GB = (NN + 127) / 128;

    // conv1 (fused): h1 = relu(agg@W1r^T + x@W1x^T + b1) -> fp16
    k_agg1<<<AGG_GRID, 256>>>();
    k_gemm<<<GB, 256, GEMM_SMEM>>>(agg, 0, xh, 1, b1, FL_RELU, h1);

    // conv2: hq2 = (h1@W2^T)*dinv -> fp16; h2 = relu(dinv*(sum)+b2) -> fp16
    k_gemm<<<GB, 256, GEMM_SMEM>>>(h1, 2, nullptr, 0, nullptr, FL_DINV, hq);
    k_aggn<<<AGG_GRID, 256>>>(b2, 1, 1);

    // conv3: hq3 = (h2@W3^T)*dinv -> fp16; h3 = dinv*(sum)+b3 -> fp16 g_h3
    k_gemm<<<GB, 256, GEMM_SMEM>>>(h2, 3, nullptr, 0, nullptr, FL_DINV, hq);
    k_aggn<<<AGG_GRID, 256>>>(b3, 0, 0);

    // pooling + normalize + classifier
    k_pool2<<<(NN + 63) / 64, 128>>>(batch);
    k_final<<<GG, HH>>>(batch, Wl, bl, out);
}

// round 16
// speedup vs baseline: 1.8853x; 1.0429x over previous
#include <cuda_runtime.h>
#include <cuda_fp16.h>
#include <math.h>
#include <cstdint>

#define NN 50000
#define EE 800000
#define HH 128
#define GG 128
#define CC 10
#define SCAN_BLK 49   // ceil(50000/1024)

// ---------------- static device scratch ----------------
__device__ int      g_deg[NN];
__device__ int      g_starts[NN + 1];
__device__ int      g_part[SCAN_BLK];
__device__ int      g_cursor[NN];
__device__ int      g_src[EE];
__device__ float    g_dinv[NN];
__device__ __half   g_xh[(size_t)NN * HH];   // fp16 x
__device__ __half   g_agg[(size_t)NN * HH];  // fp16 aggregated x
__device__ __half   g_h1[(size_t)NN * HH];   // fp16 h1
__device__ __half   g_h2[(size_t)NN * HH];   // fp16 h2
__device__ __half   g_hq[(size_t)NN * HH];   // fp16 hq (conv2/3 GEMM out)
__device__ __half   g_h3[(size_t)NN * HH];   // fp16 h3 for pooling
__device__ __half   g_WcH[4 * HH * HH];      // fp16 weights hi
__device__ __half   g_WcL[4 * HH * HH];      // fp16 weights lo (residual)
__device__ float    g_pool[GG * HH];

// ---------------- fused zero + conversions ----------------
__global__ void k_zero_conv(const float4* __restrict__ x4,
                            const float* __restrict__ W0, const float* __restrict__ W1,
                            const float* __restrict__ W2, const float* __restrict__ W3) {
    int p = blockIdx.x * blockDim.x + threadIdx.x;
    if (p < NN) g_deg[p] = 0;
    if (p < GG * HH) g_pool[p] = 0.f;
    if (p < NN * HH / 4) {
        float4 v = __ldg(&x4[p]);
        __half2 a = __floats2half2_rn(v.x, v.y);
        __half2 b = __floats2half2_rn(v.z, v.w);
        uint2 o; o.x = *(uint32_t*)&a; o.y = *(uint32_t*)&b;
        *(uint2*)&g_xh[(size_t)p * 4] = o;
    }
    if (p < HH * HH) {
        const float* Ws[4] = {W0, W1, W2, W3};
        #pragma unroll
        for (int w = 0; w < 4; w++) {
            float v = __ldg(&Ws[w][p]);
            __half h = __float2half(v);
            g_WcH[w * HH * HH + p] = h;
            g_WcL[w * HH * HH + p] = __float2half(v - __half2float(h));
        }
    }
}

// degree count: 4 edges per thread
__global__ void k_deg(const int4* __restrict__ col4) {
    int t = blockIdx.x * blockDim.x + threadIdx.x;
    if (t < EE / 4) {
        int4 c = __ldg(&col4[t]);
        atomicAdd(&g_deg[c.x], 1);
        atomicAdd(&g_deg[c.y], 1);
        atomicAdd(&g_deg[c.z], 1);
        atomicAdd(&g_deg[c.w], 1);
    }
}

// ---- scan phase 1: per-block exclusive scan + block totals ----
__global__ void k_part() {
    __shared__ int warp_sums[32];
    int tid = threadIdx.x;
    int lane = tid & 31, wid = tid >> 5;
    int i = blockIdx.x * 1024 + tid;
    int v = (i < NN) ? g_deg[i] : 0;
    int s = v;
    #pragma unroll
    for (int o = 1; o < 32; o <<= 1) {
        int t = __shfl_up_sync(0xFFFFFFFFu, s, o);
        if (lane >= o) s += t;
    }
    if (lane == 31) warp_sums[wid] = s;
    __syncthreads();
    if (wid == 0) {
        int ws = warp_sums[lane];
        #pragma unroll
        for (int o = 1; o < 32; o <<= 1) {
            int t = __shfl_up_sync(0xFFFFFFFFu, ws, o);
            if (lane >= o) ws += t;
        }
        warp_sums[lane] = ws;
    }
    __syncthreads();
    int offset = (wid > 0) ? warp_sums[wid - 1] : 0;
    if (i < NN) g_starts[i] = offset + s - v;
    if (tid == 1023) g_part[blockIdx.x] = offset + s;
}

// ---- scan phase 2 fused: block-offset add + dinv + cursor ----
__global__ void k_addoff2() {
    __shared__ int s_part[SCAN_BLK];
    int tid = threadIdx.x, bid = blockIdx.x;
    if (tid < SCAN_BLK) s_part[tid] = g_part[tid];
    __syncthreads();
    int off = 0;
    for (int j = 0; j < bid; j++) off += s_part[j];
    int i = bid * 1024 + tid;
    if (i < NN) {
        int st = g_starts[i] + off;
        g_starts[i] = st;
        g_cursor[i] = st;
        g_dinv[i] = rsqrtf((float)(g_deg[i] + 1));
    }
    if (bid == SCAN_BLK - 1 && tid == 0)
        g_starts[NN] = off + s_part[SCAN_BLK - 1];
}

// CSR fill: 4 edges per thread
__global__ void k_fill(const int4* __restrict__ row4, const int4* __restrict__ col4) {
    int t = blockIdx.x * blockDim.x + threadIdx.x;
    if (t < EE / 4) {
        int4 r = __ldg(&row4[t]);
        int4 c = __ldg(&col4[t]);
        int p0 = atomicAdd(&g_cursor[c.x], 1);
        int p1 = atomicAdd(&g_cursor[c.y], 1);
        int p2 = atomicAdd(&g_cursor[c.z], 1);
        int p3 = atomicAdd(&g_cursor[c.w], 1);
        g_src[p0] = r.x;
        g_src[p1] = r.y;
        g_src[p2] = r.z;
        g_src[p3] = r.w;
    }
}

// ---------------- aggregation (half-warp per node, fp16 HADD2 accumulation) ----------------
__device__ __forceinline__ void hacc4(uint4& acc, uint4 v) {
    __half2* a = (__half2*)&acc;
    const __half2* b = (const __half2*)&v;
    a[0] = __hadd2(a[0], b[0]);
    a[1] = __hadd2(a[1], b[1]);
    a[2] = __hadd2(a[2], b[2]);
    a[3] = __hadd2(a[3], b[3]);
}

// gather x (fp16) -> g_agg; fp16 accumulate, direct store
__global__ void k_agg1() {
    int node = blockIdx.x * 16 + (threadIdx.x >> 4);
    if (node >= NN) return;
    int sub = threadIdx.x & 15;
    const uint4* xh = (const uint4*)g_xh;
    uint4 acc = make_uint4(0u, 0u, 0u, 0u);
    int s = g_starts[node], e = g_starts[node + 1];
    #pragma unroll 8
    for (int j = s; j < e; j++) {
        int u = __ldg(&g_src[j]);
        hacc4(acc, __ldg(&xh[(size_t)u * 16 + sub]));
    }
    *(uint4*)&g_agg[(size_t)node * HH + sub * 8] = acc;
}

// gather g_hq (fp16), self+neigh (fp16 acc), *dinv, +bias (fp32), optional relu; fp16 out
__global__ void k_aggn(const float* __restrict__ bias, int relu, int mode) {
    int node = blockIdx.x * 16 + (threadIdx.x >> 4);
    if (node >= NN) return;
    int sub = threadIdx.x & 15;
    const uint4* hq = (const uint4*)g_hq;
    uint4 acc = __ldg(&hq[(size_t)node * 16 + sub]);  // self
    int s = g_starts[node], e = g_starts[node + 1];
    #pragma unroll 8
    for (int j = s; j < e; j++) {
        int u = __ldg(&g_src[j]);
        hacc4(acc, __ldg(&hq[(size_t)u * 16 + sub]));
    }
    // fp32 epilogue (once per node)
    __half2* ah = (__half2*)&acc;
    float2 f0 = __half22float2(ah[0]);
    float2 f1 = __half22float2(ah[1]);
    float2 f2 = __half22float2(ah[2]);
    float2 f3 = __half22float2(ah[3]);
    float dv = g_dinv[node];
    float4 b0 = __ldg(&((const float4*)bias)[sub * 2]);
    float4 b1 = __ldg(&((const float4*)bias)[sub * 2 + 1]);
    float r0 = fmaf(f0.x, dv, b0.x), r1 = fmaf(f0.y, dv, b0.y);
    float r2 = fmaf(f1.x, dv, b0.z), r3 = fmaf(f1.y, dv, b0.w);
    float r4 = fmaf(f2.x, dv, b1.x), r5 = fmaf(f2.y, dv, b1.y);
    float r6 = fmaf(f3.x, dv, b1.z), r7 = fmaf(f3.y, dv, b1.w);
    if (relu) {
        r0 = fmaxf(r0, 0.f); r1 = fmaxf(r1, 0.f); r2 = fmaxf(r2, 0.f); r3 = fmaxf(r3, 0.f);
        r4 = fmaxf(r4, 0.f); r5 = fmaxf(r5, 0.f); r6 = fmaxf(r6, 0.f); r7 = fmaxf(r7, 0.f);
    }
    __half2 o0 = __floats2half2_rn(r0, r1);
    __half2 o1 = __floats2half2_rn(r2, r3);
    __half2 o2 = __floats2half2_rn(r4, r5);
    __half2 o3 = __floats2half2_rn(r6, r7);
    uint4 o;
    o.x = *(uint32_t*)&o0; o.y = *(uint32_t*)&o1;
    o.z = *(uint32_t*)&o2; o.w = *(uint32_t*)&o3;
    __half* dst = mode ? g_h2 : g_h3;
    *(uint4*)&dst[(size_t)node * HH + sub * 8] = o;
}

// ---------------- HMMA GEMM (fp16 A, split-fp16 W, ldmatrix) ----------------
#define FL_RELU 2
#define FL_DINV 4
#define APITCH 136
#define GEMM_SMEM (3 * 128 * APITCH * 2)

__device__ __forceinline__ uint32_t smem_u32(const void* p) {
    uint32_t a;
    asm("{ .reg .u64 t; cvta.to.shared.u64 t, %1; cvt.u32.u64 %0, t; }" : "=r"(a) : "l"(p));
    return a;
}
__device__ __forceinline__ void ldsm_x4(uint32_t& r0, uint32_t& r1, uint32_t& r2, uint32_t& r3,
                                        uint32_t addr) {
    asm volatile("ldmatrix.sync.aligned.m8n8.x4.shared.b16 {%0,%1,%2,%3}, [%4];"
        : "=r"(r0), "=r"(r1), "=r"(r2), "=r"(r3) : "r"(addr));
}
__device__ __forceinline__ void mma16816(float* c, const uint32_t* a, uint32_t b0, uint32_t b1) {
    asm volatile("mma.sync.aligned.m16n8k16.row.col.f32.f16.f16.f32 "
        "{%0,%1,%2,%3}, {%4,%5,%6,%7}, {%8,%9}, {%0,%1,%2,%3};"
        : "+f"(c[0]), "+f"(c[1]), "+f"(c[2]), "+f"(c[3])
        : "r"(a[0]), "r"(a[1]), "r"(a[2]), "r"(a[3]), "r"(b0), "r"(b1));
}

// copy fp16 tile [128 x 128] global -> padded smem (16B vectors)
__device__ __forceinline__ void load_tile16(__half* dst, const __half* src, int m0,
                                            int bound, int tid) {
    const uint4* s4 = (const uint4*)src;
    #pragma unroll 2
    for (int p = tid; p < 2048; p += 256) {
        int row = p >> 4, c8 = p & 15;
        int m = m0 + row;
        uint4 v = make_uint4(0u, 0u, 0u, 0u);
        if (m < bound) v = __ldg(&s4[(size_t)m * 16 + c8]);
        *(uint4*)&dst[row * APITCH + c8 * 8] = v;
    }
}

struct Frag { float c[2][8][4]; };

// one stage-pair: f += A*Wh^T + A*Wl^T
__device__ __forceinline__ void mma_stage2(Frag& f, uint32_t aBase, uint32_t whBase,
                                           uint32_t wlBase, int wm, int wn, int lane) {
    int lr = lane & 7, q = lane >> 3;
    int arow = wm + ((q & 1) << 3) + lr;
    int acol = (q >> 1) << 3;
    int brow = wn + ((q >> 1) << 3) + lr;
    int bcol = (q & 1) << 3;
    #pragma unroll
    for (int ks = 0; ks < 8; ks++) {
        int kb0 = ks * 16;
        uint32_t a[2][4];
        #pragma unroll
        for (int mt = 0; mt < 2; mt++) {
            uint32_t addr = aBase + (uint32_t)(((arow + mt * 16) * APITCH + kb0 + acol) * 2);
            ldsm_x4(a[mt][0], a[mt][1], a[mt][2], a[mt][3], addr);
        }
        #pragma unroll
        for (int pass = 0; pass < 2; pass++) {
            uint32_t wBase = pass ? wlBase : whBase;
            #pragma unroll
            for (int ntp = 0; ntp < 4; ntp++) {
                uint32_t addr = wBase + (uint32_t)(((brow + ntp * 16) * APITCH + kb0 + bcol) * 2);
                uint32_t b0e, b1e, b0o, b1o;
                ldsm_x4(b0e, b1e, b0o, b1o, addr);
                mma16816(f.c[0][2 * ntp],     a[0], b0e, b1e);
                mma16816(f.c[1][2 * ntp],     a[1], b0e, b1e);
                mma16816(f.c[0][2 * ntp + 1], a[0], b0o, b1o);
                mma16816(f.c[1][2 * ntp + 1], a[1], b0o, b1o);
            }
        }
    }
}

// C[M,128] = A@W[w0]^T (+ A2@W[w1]^T) (+bias) (*dinv) (relu) -> fp16 out
__global__ __launch_bounds__(256, 2) void k_gemm(
    const __half* __restrict__ A, int w0,
    const __half* __restrict__ A2, int w1,
    const float* __restrict__ bias, int flags,
    __half* __restrict__ outp)
{
    extern __shared__ __half sm[];
    __half* Ah = sm;
    __half* Wh = Ah + 128 * APITCH;
    __half* Wl = Wh + 128 * APITCH;
    int tid = threadIdx.x, wid = tid >> 5, lane = tid & 31;
    int m0 = blockIdx.x * 128;
    int wm = (wid & 3) * 32;
    int wn = (wid >> 2) * 64;
    int g = lane >> 2, tig = lane & 3;
    uint32_t aBase = smem_u32(Ah), whBase = smem_u32(Wh), wlBase = smem_u32(Wl);

    Frag f;
    #pragma unroll
    for (int mt = 0; mt < 2; mt++)
        #pragma unroll
        for (int nt = 0; nt < 8; nt++)
            #pragma unroll
            for (int j = 0; j < 4; j++) f.c[mt][nt][j] = 0.f;

    load_tile16(Ah, A, m0, NN, tid);
    load_tile16(Wh, g_WcH + (size_t)w0 * HH * HH, 0, HH, tid);
    load_tile16(Wl, g_WcL + (size_t)w0 * HH * HH, 0, HH, tid);
    __syncthreads();
    mma_stage2(f, aBase, whBase, wlBase, wm, wn, lane);

    if (A2) {
        __syncthreads();
        load_tile16(Ah, A2, m0, NN, tid);
        load_tile16(Wh, g_WcH + (size_t)w1 * HH * HH, 0, HH, tid);
        load_tile16(Wl, g_WcL + (size_t)w1 * HH * HH, 0, HH, tid);
        __syncthreads();
        mma_stage2(f, aBase, whBase, wlBase, wm, wn, lane);
    }

    #pragma unroll
    for (int mt = 0; mt < 2; mt++) {
        #pragma unroll
        for (int half = 0; half < 2; half++) {
            int m = m0 + wm + mt * 16 + g + half * 8;
            if (m >= NN) continue;
            float dv = (flags & FL_DINV) ? g_dinv[m] : 1.f;
            #pragma unroll
            for (int nt = 0; nt < 8; nt++) {
                int col = wn + nt * 8 + 2 * tig;
                float vx = f.c[mt][nt][half * 2 + 0];
                float vy = f.c[mt][nt][half * 2 + 1];
                if (bias) {
                    float2 b2 = __ldg((const float2*)&bias[col]);
                    vx += b2.x; vy += b2.y;
                }
                if (flags & FL_DINV) { vx *= dv; vy *= dv; }
                if (flags & FL_RELU) { vx = fmaxf(vx, 0.f); vy = fmaxf(vy, 0.f); }
                __half2 hv = __floats2half2_rn(vx, vy);
                *(__half2*)&outp[(size_t)m * HH + col] = hv;
            }
        }
    }
}

// ---------------- pooling (fp16 input) + fused finalize ----------------
__global__ void k_pool2(const int* __restrict__ batch) {
    const __half* h = g_h3;
    int c = threadIdx.x;
    int n0 = blockIdx.x * 64;
    int n1 = n0 + 64; if (n1 > NN) n1 = NN;
    if (n0 >= NN) return;
    float acc = 0.f;
    int cur = __ldg(&batch[n0]);
    for (int n = n0; n < n1; n++) {
        int b = __ldg(&batch[n]);
        if (b != cur) { atomicAdd(&g_pool[cur * HH + c], acc); acc = 0.f; cur = b; }
        acc += __half2float(__ldg(&h[(size_t)n * HH + c]));
    }
    atomicAdd(&g_pool[cur * HH + c], acc);
}

// lower_bound on sorted batch: first i with batch[i] >= val
__device__ __forceinline__ int lb_batch(const int* __restrict__ batch, int val) {
    int lo = 0, hi = NN;
    while (lo < hi) {
        int mid = (lo + hi) >> 1;
        if (__ldg(&batch[mid]) < val) lo = mid + 1; else hi = mid;
    }
    return lo;
}

__global__ void k_final(const int* __restrict__ batch,
                        const float* __restrict__ Wl, const float* __restrict__ bl,
                        float* __restrict__ dout) {
    __shared__ float ws[4];
    __shared__ float xs[HH];
    __shared__ float winv[CC];
    int g = blockIdx.x, t = threadIdx.x;
    int cnt = lb_batch(batch, g + 1) - lb_batch(batch, g);
    float c = fmaxf((float)cnt, 1.f);
    float v = g_pool[g * HH + t] / c;
    float s = v * v;
    #pragma unroll
    for (int o = 16; o > 0; o >>= 1) s += __shfl_down_sync(0xFFFFFFFFu, s, o);
    if ((t & 31) == 0) ws[t >> 5] = s;
    if (t < CC) {
        float sw = 0.f;
        #pragma unroll 8
        for (int k = 0; k < HH; k++) { float w = __ldg(&Wl[t * HH + k]); sw = fmaf(w, w, sw); }
        winv[t] = 1.f / fmaxf(sqrtf(sw), 1e-12f);
    }
    __syncthreads();
    float tot = ws[0] + ws[1] + ws[2] + ws[3];
    float nrm = fmaxf(sqrtf(tot), 1e-12f);
    float xn = v / nrm;
    dout[g * HH + t] = xn;
    xs[t] = xn;
    __syncthreads();
    if (t < CC) {
        float s2 = 0.f;
        #pragma unroll 8
        for (int k = 0; k < HH; k++) s2 = fmaf(xs[k], __ldg(&Wl[t * HH + k]), s2);
        dout[GG * HH + g * CC + t] = fmaf(s2, winv[t], bl[t]);
    }
}

// ---------------- launch ----------------
extern "C" void kernel_launch(void* const* d_in, const int* in_sizes, int n_in,
                              void* d_out, int out_size) {
    const float* x    = (const float*)d_in[0];
    const int*   ei   = (const int*)d_in[1];
    const int*   batch= (const int*)d_in[2];
    const float* W1r  = (const float*)d_in[3];
    const float* b1   = (const float*)d_in[4];
    const float* W1x  = (const float*)d_in[5];
    const float* W2   = (const float*)d_in[6];
    const float* b2   = (const float*)d_in[7];
    const float* W3   = (const float*)d_in[8];
    const float* b3   = (const float*)d_in[9];
    const float* Wl   = (const float*)d_in[10];
    const float* bl   = (const float*)d_in[11];
    const int* row = ei;
    const int* col = ei + EE;
    float* out = (float*)d_out;

    cudaFuncSetAttribute(k_gemm, cudaFuncAttributeMaxDynamicSharedMemorySize, GEMM_SMEM);

    __half *xh, *agg, *h1, *h2, *hq;
    cudaGetSymbolAddress((void**)&xh, g_xh);
    cudaGetSymbolAddress((void**)&agg, g_agg);
    cudaGetSymbolAddress((void**)&h1, g_h1);
    cudaGetSymbolAddress((void**)&h2, g_h2);
    cudaGetSymbolAddress((void**)&hq, g_hq);

    // preprocessing
    k_zero_conv<<<(NN * HH / 4 + 255) / 256, 256>>>((const float4*)x, W1r, W1x, W2, W3);
    k_deg<<<(EE / 4 + 255) / 256, 256>>>((const int4*)col);
    k_part<<<SCAN_BLK, 1024>>>();
    k_addoff2<<<SCAN_BLK, 1024>>>();
    k_fill<<<(EE / 4 + 255) / 256, 256>>>((const int4*)row, (const int4*)col);

    int AGG_GRID = (NN + 15) / 16;
    int GB = (NN + 127) / 128;

    // conv1 (fused): h1 = relu(agg@W1r^T + x@W1x^T + b1) -> fp16
    k_agg1<<<AGG_GRID, 256>>>();
    k_gemm<<<GB, 256, GEMM_SMEM>>>(agg, 0, xh, 1, b1, FL_RELU, h1);

    // conv2: hq2 = (h1@W2^T)*dinv -> fp16; h2 = relu(dinv*(sum)+b2) -> fp16
    k_gemm<<<GB, 256, GEMM_SMEM>>>(h1, 2, nullptr, 0, nullptr, FL_DINV, hq);
    k_aggn<<<AGG_GRID, 256>>>(b2, 1, 1);

    // conv3: hq3 = (h2@W3^T)*dinv -> fp16; h3 = dinv*(sum)+b3 -> fp16 g_h3
    k_gemm<<<GB, 256, GEMM_SMEM>>>(h2, 3, nullptr, 0, nullptr, FL_DINV, hq);
    k_aggn<<<AGG_GRID, 256>>>(b3, 0, 0);

    // pooling + normalize + classifier
    k_pool2<<<(NN + 63) / 64, 128>>>(batch);
    k_final<<<GG, HH>>>(batch, Wl, bl, out);
}

// round 17
// speedup vs baseline: 1.9109x; 1.0136x over previous
#include <cuda_runtime.h>
#include <cuda_fp16.h>
#include <math.h>
#include <cstdint>

#define NN 50000
#define EE 800000
#define HH 128
#define GG 128
#define CC 10
#define SCAN_BLK 49   // ceil(50000/1024)

// ---------------- static device scratch ----------------
__device__ int      g_deg[NN];
__device__ int      g_starts[NN + 1];
__device__ int      g_part[SCAN_BLK];
__device__ int      g_cursor[NN];
__device__ int      g_src[EE];
__device__ float    g_dinv[NN];
__device__ __half   g_agg[(size_t)NN * HH];  // fp16 aggregated x
__device__ __half   g_h1[(size_t)NN * HH];   // fp16 h1
__device__ __half   g_h2[(size_t)NN * HH];   // fp16 h2
__device__ __half   g_hq[(size_t)NN * HH];   // fp16 hq (conv2/3 GEMM out)
__device__ __half   g_WcH[4 * HH * HH];      // fp16 weights hi
__device__ __half   g_WcL[4 * HH * HH];      // fp16 weights lo (residual)
__device__ float    g_pool[GG * HH];

// ---------------- zero + weight conversion (small) ----------------
__global__ void k_zero_conv(const float* __restrict__ W0, const float* __restrict__ W1,
                            const float* __restrict__ W2, const float* __restrict__ W3) {
    int p = blockIdx.x * blockDim.x + threadIdx.x;
    if (p < NN) g_deg[p] = 0;
    if (p < GG * HH) g_pool[p] = 0.f;
    if (p < HH * HH) {
        const float* Ws[4] = {W0, W1, W2, W3};
        #pragma unroll
        for (int w = 0; w < 4; w++) {
            float v = __ldg(&Ws[w][p]);
            __half h = __float2half(v);
            g_WcH[w * HH * HH + p] = h;
            g_WcL[w * HH * HH + p] = __float2half(v - __half2float(h));
        }
    }
}

// degree count: 4 edges per thread
__global__ void k_deg(const int4* __restrict__ col4) {
    int t = blockIdx.x * blockDim.x + threadIdx.x;
    if (t < EE / 4) {
        int4 c = __ldg(&col4[t]);
        atomicAdd(&g_deg[c.x], 1);
        atomicAdd(&g_deg[c.y], 1);
        atomicAdd(&g_deg[c.z], 1);
        atomicAdd(&g_deg[c.w], 1);
    }
}

// ---- scan phase 1: per-block exclusive scan + block totals ----
__global__ void k_part() {
    __shared__ int warp_sums[32];
    int tid = threadIdx.x;
    int lane = tid & 31, wid = tid >> 5;
    int i = blockIdx.x * 1024 + tid;
    int v = (i < NN) ? g_deg[i] : 0;
    int s = v;
    #pragma unroll
    for (int o = 1; o < 32; o <<= 1) {
        int t = __shfl_up_sync(0xFFFFFFFFu, s, o);
        if (lane >= o) s += t;
    }
    if (lane == 31) warp_sums[wid] = s;
    __syncthreads();
    if (wid == 0) {
        int ws = warp_sums[lane];
        #pragma unroll
        for (int o = 1; o < 32; o <<= 1) {
            int t = __shfl_up_sync(0xFFFFFFFFu, ws, o);
            if (lane >= o) ws += t;
        }
        warp_sums[lane] = ws;
    }
    __syncthreads();
    int offset = (wid > 0) ? warp_sums[wid - 1] : 0;
    if (i < NN) g_starts[i] = offset + s - v;
    if (tid == 1023) g_part[blockIdx.x] = offset + s;
}

// ---- scan phase 2 fused: block-offset add + dinv + cursor ----
__global__ void k_addoff2() {
    __shared__ int s_part[SCAN_BLK];
    int tid = threadIdx.x, bid = blockIdx.x;
    if (tid < SCAN_BLK) s_part[tid] = g_part[tid];
    __syncthreads();
    int off = 0;
    for (int j = 0; j < bid; j++) off += s_part[j];
    int i = bid * 1024 + tid;
    if (i < NN) {
        int st = g_starts[i] + off;
        g_starts[i] = st;
        g_cursor[i] = st;
        g_dinv[i] = rsqrtf((float)(g_deg[i] + 1));
    }
    if (bid == SCAN_BLK - 1 && tid == 0)
        g_starts[NN] = off + s_part[SCAN_BLK - 1];
}

// CSR fill: 4 edges per thread
__global__ void k_fill(const int4* __restrict__ row4, const int4* __restrict__ col4) {
    int t = blockIdx.x * blockDim.x + threadIdx.x;
    if (t < EE / 4) {
        int4 r = __ldg(&row4[t]);
        int4 c = __ldg(&col4[t]);
        int p0 = atomicAdd(&g_cursor[c.x], 1);
        int p1 = atomicAdd(&g_cursor[c.y], 1);
        int p2 = atomicAdd(&g_cursor[c.z], 1);
        int p3 = atomicAdd(&g_cursor[c.w], 1);
        g_src[p0] = r.x;
        g_src[p1] = r.y;
        g_src[p2] = r.z;
        g_src[p3] = r.w;
    }
}

// ---------------- aggregation ----------------
__device__ __forceinline__ void hacc4(uint4& acc, uint4 v) {
    __half2* a = (__half2*)&acc;
    const __half2* b = (const __half2*)&v;
    a[0] = __hadd2(a[0], b[0]);
    a[1] = __hadd2(a[1], b[1]);
    a[2] = __hadd2(a[2], b[2]);
    a[3] = __hadd2(a[3], b[3]);
}
__device__ __forceinline__ void store_half8(__half* dst, size_t idx, float4 a, float4 b) {
    __half2 h0 = __floats2half2_rn(a.x, a.y);
    __half2 h1 = __floats2half2_rn(a.z, a.w);
    __half2 h2 = __floats2half2_rn(b.x, b.y);
    __half2 h3 = __floats2half2_rn(b.z, b.w);
    uint4 o;
    o.x = *(uint32_t*)&h0; o.y = *(uint32_t*)&h1;
    o.z = *(uint32_t*)&h2; o.w = *(uint32_t*)&h3;
    *(uint4*)&dst[idx] = o;
}

// gather x (fp32 direct) -> g_agg (fp16); half-warp per node
__global__ void k_agg1(const float4* __restrict__ x4) {
    int node = blockIdx.x * 16 + (threadIdx.x >> 4);
    if (node >= NN) return;
    int sub = threadIdx.x & 15;
    float4 a0 = make_float4(0.f, 0.f, 0.f, 0.f);
    float4 a1 = make_float4(0.f, 0.f, 0.f, 0.f);
    int s = g_starts[node], e = g_starts[node + 1];
    #pragma unroll 4
    for (int j = s; j < e; j++) {
        int u = __ldg(&g_src[j]);
        float4 v0 = __ldg(&x4[(size_t)u * 32 + sub * 2]);
        float4 v1 = __ldg(&x4[(size_t)u * 32 + sub * 2 + 1]);
        a0.x += v0.x; a0.y += v0.y; a0.z += v0.z; a0.w += v0.w;
        a1.x += v1.x; a1.y += v1.y; a1.z += v1.z; a1.w += v1.w;
    }
    store_half8(g_agg, (size_t)node * HH + sub * 8, a0, a1);
}

// gather g_hq (fp16 acc), *dinv, +bias, relu?; mode1 -> g_h2; mode0 -> fused pooling
__global__ void k_aggn(const float* __restrict__ bias, int relu, int mode,
                       const int* __restrict__ batch) {
    __shared__ float sp[16][HH];   // 8 KB
    __shared__ int sb[16];
    int tid = threadIdx.x;
    int hw = tid >> 4, sub = tid & 15;
    int node = blockIdx.x * 16 + hw;   // NN = 16*3125 exactly -> always valid
    const uint4* hq = (const uint4*)g_hq;
    uint4 acc = __ldg(&hq[(size_t)node * 16 + sub]);  // self
    int s = g_starts[node], e = g_starts[node + 1];
    #pragma unroll 8
    for (int j = s; j < e; j++) {
        int u = __ldg(&g_src[j]);
        hacc4(acc, __ldg(&hq[(size_t)u * 16 + sub]));
    }
    __half2* ah = (__half2*)&acc;
    float2 f0 = __half22float2(ah[0]);
    float2 f1 = __half22float2(ah[1]);
    float2 f2 = __half22float2(ah[2]);
    float2 f3 = __half22float2(ah[3]);
    float dv = g_dinv[node];
    float4 b0 = __ldg(&((const float4*)bias)[sub * 2]);
    float4 b1 = __ldg(&((const float4*)bias)[sub * 2 + 1]);
    float4 r0, r1;
    r0.x = fmaf(f0.x, dv, b0.x); r0.y = fmaf(f0.y, dv, b0.y);
    r0.z = fmaf(f1.x, dv, b0.z); r0.w = fmaf(f1.y, dv, b0.w);
    r1.x = fmaf(f2.x, dv, b1.x); r1.y = fmaf(f2.y, dv, b1.y);
    r1.z = fmaf(f3.x, dv, b1.z); r1.w = fmaf(f3.y, dv, b1.w);
    if (relu) {
        r0.x = fmaxf(r0.x, 0.f); r0.y = fmaxf(r0.y, 0.f);
        r0.z = fmaxf(r0.z, 0.f); r0.w = fmaxf(r0.w, 0.f);
        r1.x = fmaxf(r1.x, 0.f); r1.y = fmaxf(r1.y, 0.f);
        r1.z = fmaxf(r1.z, 0.f); r1.w = fmaxf(r1.w, 0.f);
    }
    if (mode) {
        store_half8(g_h2, (size_t)node * HH + sub * 8, r0, r1);
        return;
    }
    // mode 0: fused mean-pool accumulation (batch sorted -> run-length in block)
    *(float4*)&sp[hw][sub * 8] = r0;
    *(float4*)&sp[hw][sub * 8 + 4] = r1;
    if (sub == 0) sb[hw] = __ldg(&batch[node]);
    __syncthreads();
    int f = tid;
    if (f < HH) {
        float acc2 = 0.f;
        int cur = sb[0];
        #pragma unroll
        for (int i = 0; i < 16; i++) {
            int b = sb[i];
            if (b != cur) { atomicAdd(&g_pool[cur * HH + f], acc2); acc2 = 0.f; cur = b; }
            acc2 += sp[i][f];
        }
        atomicAdd(&g_pool[cur * HH + f], acc2);
    }
}

// ---------------- HMMA GEMM (fp16 A, split-fp16 W, ldmatrix) ----------------
#define FL_RELU 2
#define FL_DINV 4
#define APITCH 136
#define GEMM_SMEM (3 * 128 * APITCH * 2)

__device__ __forceinline__ uint32_t smem_u32(const void* p) {
    uint32_t a;
    asm("{ .reg .u64 t; cvta.to.shared.u64 t, %1; cvt.u32.u64 %0, t; }" : "=r"(a) : "l"(p));
    return a;
}
__device__ __forceinline__ void ldsm_x4(uint32_t& r0, uint32_t& r1, uint32_t& r2, uint32_t& r3,
                                        uint32_t addr) {
    asm volatile("ldmatrix.sync.aligned.m8n8.x4.shared.b16 {%0,%1,%2,%3}, [%4];"
        : "=r"(r0), "=r"(r1), "=r"(r2), "=r"(r3) : "r"(addr));
}
__device__ __forceinline__ void mma16816(float* c, const uint32_t* a, uint32_t b0, uint32_t b1) {
    asm volatile("mma.sync.aligned.m16n8k16.row.col.f32.f16.f16.f32 "
        "{%0,%1,%2,%3}, {%4,%5,%6,%7}, {%8,%9}, {%0,%1,%2,%3};"
        : "+f"(c[0]), "+f"(c[1]), "+f"(c[2]), "+f"(c[3])
        : "r"(a[0]), "r"(a[1]), "r"(a[2]), "r"(a[3]), "r"(b0), "r"(b1));
}

// copy fp16 tile [128 x 128] global -> padded smem (16B vectors)
__device__ __forceinline__ void load_tile16(__half* dst, const __half* src, int m0,
                                            int bound, int tid) {
    const uint4* s4 = (const uint4*)src;
    #pragma unroll 2
    for (int p = tid; p < 2048; p += 256) {
        int row = p >> 4, c8 = p & 15;
        int m = m0 + row;
        uint4 v = make_uint4(0u, 0u, 0u, 0u);
        if (m < bound) v = __ldg(&s4[(size_t)m * 16 + c8]);
        *(uint4*)&dst[row * APITCH + c8 * 8] = v;
    }
}

// convert fp32 tile -> fp16 padded smem
__device__ __forceinline__ void load_tile_f32(__half* dst, const float* src, int m0, int tid) {
    const float4* s4 = (const float4*)src;
    #pragma unroll 2
    for (int p = tid; p < 2048; p += 256) {
        int row = p >> 4, c8 = p & 15;
        int m = m0 + row;
        float4 va = make_float4(0.f, 0.f, 0.f, 0.f);
        float4 vb = make_float4(0.f, 0.f, 0.f, 0.f);
        if (m < NN) {
            va = __ldg(&s4[(size_t)m * 32 + c8 * 2]);
            vb = __ldg(&s4[(size_t)m * 32 + c8 * 2 + 1]);
        }
        __half2 h0 = __floats2half2_rn(va.x, va.y);
        __half2 h1 = __floats2half2_rn(va.z, va.w);
        __half2 h2 = __floats2half2_rn(vb.x, vb.y);
        __half2 h3 = __floats2half2_rn(vb.z, vb.w);
        uint4 o;
        o.x = *(uint32_t*)&h0; o.y = *(uint32_t*)&h1;
        o.z = *(uint32_t*)&h2; o.w = *(uint32_t*)&h3;
        *(uint4*)&dst[row * APITCH + c8 * 8] = o;
    }
}

struct Frag { float c[2][8][4]; };

// one stage-pair: f += A*Wh^T + A*Wl^T
__device__ __forceinline__ void mma_stage2(Frag& f, uint32_t aBase, uint32_t whBase,
                                           uint32_t wlBase, int wm, int wn, int lane) {
    int lr = lane & 7, q = lane >> 3;
    int arow = wm + ((q & 1) << 3) + lr;
    int acol = (q >> 1) << 3;
    int brow = wn + ((q >> 1) << 3) + lr;
    int bcol = (q & 1) << 3;
    #pragma unroll
    for (int ks = 0; ks < 8; ks++) {
        int kb0 = ks * 16;
        uint32_t a[2][4];
        #pragma unroll
        for (int mt = 0; mt < 2; mt++) {
            uint32_t addr = aBase + (uint32_t)(((arow + mt * 16) * APITCH + kb0 + acol) * 2);
            ldsm_x4(a[mt][0], a[mt][1], a[mt][2], a[mt][3], addr);
        }
        #pragma unroll
        for (int pass = 0; pass < 2; pass++) {
            uint32_t wBase = pass ? wlBase : whBase;
            #pragma unroll
            for (int ntp = 0; ntp < 4; ntp++) {
                uint32_t addr = wBase + (uint32_t)(((brow + ntp * 16) * APITCH + kb0 + bcol) * 2);
                uint32_t b0e, b1e, b0o, b1o;
                ldsm_x4(b0e, b1e, b0o, b1o, addr);
                mma16816(f.c[0][2 * ntp],     a[0], b0e, b1e);
                mma16816(f.c[1][2 * ntp],     a[1], b0e, b1e);
                mma16816(f.c[0][2 * ntp + 1], a[0], b0o, b1o);
                mma16816(f.c[1][2 * ntp + 1], a[1], b0o, b1o);
            }
        }
    }
}

// C[M,128] = A@W[w0]^T (+ x2f@W[w1]^T, fp32 src) (+bias) (*dinv) (relu) -> fp16 out
__global__ __launch_bounds__(256, 2) void k_gemm(
    const __half* __restrict__ A, int w0,
    const float* __restrict__ x2f, int w1,
    const float* __restrict__ bias, int flags,
    __half* __restrict__ outp)
{
    extern __shared__ __half sm[];
    __half* Ah = sm;
    __half* Wh = Ah + 128 * APITCH;
    __half* Wl = Wh + 128 * APITCH;
    int tid = threadIdx.x, wid = tid >> 5, lane = tid & 31;
    int m0 = blockIdx.x * 128;
    int wm = (wid & 3) * 32;
    int wn = (wid >> 2) * 64;
    int g = lane >> 2, tig = lane & 3;
    uint32_t aBase = smem_u32(Ah), whBase = smem_u32(Wh), wlBase = smem_u32(Wl);

    Frag f;
    #pragma unroll
    for (int mt = 0; mt < 2; mt++)
        #pragma unroll
        for (int nt = 0; nt < 8; nt++)
            #pragma unroll
            for (int j = 0; j < 4; j++) f.c[mt][nt][j] = 0.f;

    load_tile16(Ah, A, m0, NN, tid);
    load_tile16(Wh, g_WcH + (size_t)w0 * HH * HH, 0, HH, tid);
    load_tile16(Wl, g_WcL + (size_t)w0 * HH * HH, 0, HH, tid);
    __syncthreads();
    mma_stage2(f, aBase, whBase, wlBase, wm, wn, lane);

    if (x2f) {
        __syncthreads();
        load_tile_f32(Ah, x2f, m0, tid);
        load_tile16(Wh, g_WcH + (size_t)w1 * HH * HH, 0, HH, tid);
        load_tile16(Wl, g_WcL + (size_t)w1 * HH * HH, 0, HH, tid);
        __syncthreads();
        mma_stage2(f, aBase, whBase, wlBase, wm, wn, lane);
    }

    #pragma unroll
    for (int mt = 0; mt < 2; mt++) {
        #pragma unroll
        for (int half = 0; half < 2; half++) {
            int m = m0 + wm + mt * 16 + g + half * 8;
            if (m >= NN) continue;
            float dv = (flags & FL_DINV) ? g_dinv[m] : 1.f;
            #pragma unroll
            for (int nt = 0; nt < 8; nt++) {
                int col = wn + nt * 8 + 2 * tig;
                float vx = f.c[mt][nt][half * 2 + 0];
                float vy = f.c[mt][nt][half * 2 + 1];
                if (bias) {
                    float2 b2 = __ldg((const float2*)&bias[col]);
                    vx += b2.x; vy += b2.y;
                }
                if (flags & FL_DINV) { vx *= dv; vy *= dv; }
                if (flags & FL_RELU) { vx = fmaxf(vx, 0.f); vy = fmaxf(vy, 0.f); }
                __half2 hv = __floats2half2_rn(vx, vy);
                *(__half2*)&outp[(size_t)m * HH + col] = hv;
            }
        }
    }
}

// lower_bound on sorted batch: first i with batch[i] >= val
__device__ __forceinline__ int lb_batch(const int* __restrict__ batch, int val) {
    int lo = 0, hi = NN;
    while (lo < hi) {
        int mid = (lo + hi) >> 1;
        if (__ldg(&batch[mid]) < val) lo = mid + 1; else hi = mid;
    }
    return lo;
}

__global__ void k_final(const int* __restrict__ batch,
                        const float* __restrict__ Wl, const float* __restrict__ bl,
                        float* __restrict__ dout) {
    __shared__ float ws[4];
    __shared__ float xs[HH];
    __shared__ float winv[CC];
    int g = blockIdx.x, t = threadIdx.x;
    int cnt = lb_batch(batch, g + 1) - lb_batch(batch, g);
    float c = fmaxf((float)cnt, 1.f);
    float v = g_pool[g * HH + t] / c;
    float s = v * v;
    #pragma unroll
    for (int o = 16; o > 0; o >>= 1) s += __shfl_down_sync(0xFFFFFFFFu, s, o);
    if ((t & 31) == 0) ws[t >> 5] = s;
    if (t < CC) {
        float sw = 0.f;
        #pragma unroll 8
        for (int k = 0; k < HH; k++) { float w = __ldg(&Wl[t * HH + k]); sw = fmaf(w, w, sw); }
        winv[t] = 1.f / fmaxf(sqrtf(sw), 1e-12f);
    }
    __syncthreads();
    float tot = ws[0] + ws[1] + ws[2] + ws[3];
    float nrm = fmaxf(sqrtf(tot), 1e-12f);
    float xn = v / nrm;
    dout[g * HH + t] = xn;
    xs[t] = xn;
    __syncthreads();
    if (t < CC) {
        float s2 = 0.f;
        #pragma unroll 8
        for (int k = 0; k < HH; k++) s2 = fmaf(xs[k], __ldg(&Wl[t * HH + k]), s2);
        dout[GG * HH + g * CC + t] = fmaf(s2, winv[t], bl[t]);
    }
}

// ---------------- launch ----------------
extern "C" void kernel_launch(void* const* d_in, const int* in_sizes, int n_in,
                              void* d_out, int out_size) {
    const float* x    = (const float*)d_in[0];
    const int*   ei   = (const int*)d_in[1];
    const int*   batch= (const int*)d_in[2];
    const float* W1r  = (const float*)d_in[3];
    const float* b1   = (const float*)d_in[4];
    const float* W1x  = (const float*)d_in[5];
    const float* W2   = (const float*)d_in[6];
    const float* b2   = (const float*)d_in[7];
    const float* W3   = (const float*)d_in[8];
    const float* b3   = (const float*)d_in[9];
    const float* Wl   = (const float*)d_in[10];
    const float* bl   = (const float*)d_in[11];
    const int* row = ei;
    const int* col = ei + EE;
    float* out = (float*)d_out;

    cudaFuncSetAttribute(k_gemm, cudaFuncAttributeMaxDynamicSharedMemorySize, GEMM_SMEM);

    __half *agg, *h1, *h2, *hq;
    cudaGetSymbolAddress((void**)&agg, g_agg);
    cudaGetSymbolAddress((void**)&h1, g_h1);
    cudaGetSymbolAddress((void**)&h2, g_h2);
    cudaGetSymbolAddress((void**)&hq, g_hq);

    // preprocessing
    k_zero_conv<<<(NN + 255) / 256, 256>>>(W1r, W1x, W2, W3);
    k_deg<<<(EE / 4 + 255) / 256, 256>>>((const int4*)col);
    k_part<<<SCAN_BLK, 1024>>>();
    k_addoff2<<<SCAN_BLK, 1024>>>();
    k_fill<<<(EE / 4 + 255) / 256, 256>>>((const int4*)row, (const int4*)col);

    int AGG_GRID = (NN + 15) / 16;
    int GB = (NN + 127) / 128;

    // conv1 (fused): h1 = relu(agg@W1r^T + x@W1x^T + b1) -> fp16
    k_agg1<<<AGG_GRID, 256>>>((const float4*)x);
    k_gemm<<<GB, 256, GEMM_SMEM>>>(agg, 0, x, 1, b1, FL_RELU, h1);

    // conv2: hq2 = (h1@W2^T)*dinv -> fp16; h2 = relu(dinv*(sum)+b2) -> fp16
    k_gemm<<<GB, 256, GEMM_SMEM>>>(h1, 2, nullptr, 0, nullptr, FL_DINV, hq);
    k_aggn<<<AGG_GRID, 256>>>(b2, 1, 1, batch);

    // conv3: hq3 = (h2@W3^T)*dinv -> fp16; aggn mode0: h3 + fused mean-pool
    k_gemm<<<GB, 256, GEMM_SMEM>>>(h2, 3, nullptr, 0, nullptr, FL_DINV, hq);
    k_aggn<<<AGG_GRID, 256>>>(b3, 0, 0, batch);

    // normalize + classifier
    k_final<<<GG, HH>>>(batch, Wl, bl, out);
}